// round 9
// baseline (speedup 1.0000x reference)
#include <cuda_runtime.h>
#include <cuda_bf16.h>
#include <math.h>

#define HIDDEN   1024
#define HEADS    16
#define HEAD_DIM 64
#define BATCH    2
#define SEQ      2048
#define MROWS    (BATCH*SEQ)     // 4096
#define BH       (BATCH*HEADS)   // 32
#define KKEEP    1024

// ---------------------------------------------------------------------------
// Scratch (device globals; no runtime allocation allowed)
// ---------------------------------------------------------------------------
__device__ float    g_Q[(size_t)BH*SEQ*HEAD_DIM];
__device__ float    g_K[(size_t)BH*SEQ*HEAD_DIM];
__device__ float    g_V[(size_t)BH*SEQ*HEAD_DIM];
__device__ float    g_O[(size_t)MROWS*HIDDEN];
__device__ float    g_S[(size_t)BH*SEQ*SEQ];            // fp32 scores, 512MB
__device__ unsigned g_key16[(size_t)BH*SEQ*SEQ/2];      // u16 orderable keys
__device__ float4   g_par[(size_t)BH*SEQ];              // (kthbits, m~, 0, 0)

// ---------------------------------------------------------------------------
// MMA plumbing
// ---------------------------------------------------------------------------
__device__ __forceinline__ unsigned f2tf32(float f) {
    unsigned u;
    asm("cvt.rna.tf32.f32 %0, %1;" : "=r"(u) : "f"(f));
    return u;
}
__device__ __forceinline__ void mma8(float d[4], const uint4& a, const uint2& b) {
    asm("mma.sync.aligned.m16n8k8.row.col.f32.tf32.tf32.f32 "
        "{%0,%1,%2,%3},{%4,%5,%6,%7},{%8,%9},{%0,%1,%2,%3};"
        : "+f"(d[0]), "+f"(d[1]), "+f"(d[2]), "+f"(d[3])
        : "r"(a.x), "r"(a.y), "r"(a.z), "r"(a.w), "r"(b.x), "r"(b.y));
}
__device__ __forceinline__ void mma16(float d[4], const uint4& a, const uint2& b) {
    asm("mma.sync.aligned.m16n8k16.row.col.f32.bf16.bf16.f32 "
        "{%0,%1,%2,%3},{%4,%5,%6,%7},{%8,%9},{%0,%1,%2,%3};"
        : "+f"(d[0]), "+f"(d[1]), "+f"(d[2]), "+f"(d[3])
        : "r"(a.x), "r"(a.y), "r"(a.z), "r"(a.w), "r"(b.x), "r"(b.y));
}

// tf32 frag indexers (k8 granularity, 2 k8 per chunk16)
__device__ __forceinline__ int AIDX(int mt, int k8, int r8, int cx) {
    return ((((mt << 1) + k8) << 3) + r8) * 4 + cx;
}
__device__ __forceinline__ int BIDX(int nt, int k8, int n8, int c) {
    return ((((nt << 1) + k8) << 3) + n8) * 4 + c;
}
// bf16 frag indexers (k16 granularity)
__device__ __forceinline__ int AIDXb(int mt, int r8, int cx) {
    return ((mt << 3) + r8) * 4 + cx;
}
__device__ __forceinline__ int BIDXb(int nt, int n8, int c) {
    return ((nt << 3) + n8) * 4 + c;
}

__device__ __forceinline__ void ldrow(const float* __restrict__ p, float e[8]) {
    float4 a = *(const float4*)p;
    float4 b = *(const float4*)(p + 4);
    e[0]=a.x; e[1]=a.y; e[2]=a.z; e[3]=a.w;
    e[4]=b.x; e[5]=b.y; e[6]=b.z; e[7]=b.w;
}

__device__ __forceinline__ void bsplit(float e, unsigned short& h, unsigned short& l) {
    __nv_bfloat16 bh = __float2bfloat16(e);
    h = __bfloat16_as_ushort(bh);
    l = __bfloat16_as_ushort(__float2bfloat16(e - __bfloat162float(bh)));
}

// ---- bf16 packs (hi + lo) ----
__device__ __forceinline__ void packA16(const float e[8], uint4* Ah, uint4* Al, int tid)
{
    const int lr = tid >> 1, kh = tid & 1;
    const int mt = lr >> 4, rr = lr & 15, r8 = rr & 7, rh = rr >> 3;
    const int comp = rh + (kh << 1);
    #pragma unroll
    for (int c = 0; c < 4; ++c) {
        unsigned short h0, l0, h1, l1;
        bsplit(e[2*c],   h0, l0);
        bsplit(e[2*c+1], h1, l1);
        const int idx = AIDXb(mt, r8, c ^ (r8 & 3));
        ((unsigned*)&Ah[idx])[comp] = (unsigned)h0 | ((unsigned)h1 << 16);
        ((unsigned*)&Al[idx])[comp] = (unsigned)l0 | ((unsigned)l1 << 16);
    }
}
__device__ __forceinline__ void packB16(const float e[8], uint2* Bh, uint2* Bl, int tid)
{
    const int ln = tid >> 1, kh = tid & 1;
    const int nt = ln >> 3, n8 = ln & 7;
    #pragma unroll
    for (int c = 0; c < 4; ++c) {
        unsigned short h0, l0, h1, l1;
        bsplit(e[2*c],   h0, l0);
        bsplit(e[2*c+1], h1, l1);
        const int idx = BIDXb(nt, n8, c);
        ((unsigned*)&Bh[idx])[kh] = (unsigned)h0 | ((unsigned)h1 << 16);
        ((unsigned*)&Bl[idx])[kh] = (unsigned)l0 | ((unsigned)l1 << 16);
    }
}

// ---- tf32 packs ----
__device__ __forceinline__ void packA32(const float e[8], uint4* Ah, int tid)
{
    const int lr = tid >> 1;
    const int mt = lr >> 4, rr = lr & 15, r8 = rr & 7, rh = rr >> 3, k8 = tid & 1;
    #pragma unroll
    for (int j = 0; j < 8; ++j) {
        const int c = j & 3, ch = (j >> 2) & 1;
        const int comp = rh + (ch << 1);
        ((unsigned*)&Ah[AIDX(mt, k8, r8, c ^ (r8 & 3))])[comp] = f2tf32(e[j]);
    }
}
__device__ __forceinline__ unsigned f2u(float f) {
    unsigned b = __float_as_uint(f);
    return (b & 0x80000000u) ? ~b : (b | 0x80000000u);
}
__device__ __forceinline__ float u2f(unsigned u) {
    unsigned b = (u & 0x80000000u) ? (u & 0x7FFFFFFFu) : ~u;
    return __uint_as_float(b);
}
// gate is a plain fp32 threshold: keep iff s >= gate
__device__ __forceinline__ void packA_av(const float e[8], uint4* Ah, int tid,
                                         float gate, float m, float& psum)
{
    const int lr = tid >> 1;
    const int mt = lr >> 4, rr = lr & 15, r8 = rr & 7, rh = rr >> 3, k8 = tid & 1;
    #pragma unroll
    for (int j = 0; j < 8; ++j) {
        const float pe = (e[j] >= gate) ? __expf(e[j] - m) : 0.f;
        psum += pe;
        const int c = j & 3, ch = (j >> 2) & 1;
        const int comp = rh + (ch << 1);
        ((unsigned*)&Ah[AIDX(mt, k8, r8, c ^ (r8 & 3))])[comp] = f2tf32(pe);
    }
}
__device__ __forceinline__ void packB32_nt(const float e[8], uint2* Bh, int tid)
{
    const int ln = tid >> 1;
    const int nt = ln >> 3, n8 = ln & 7, k8 = tid & 1;
    #pragma unroll
    for (int j = 0; j < 8; ++j) {
        const int c = j & 3, ph = (j >> 2) & 1;
        ((unsigned*)&Bh[BIDX(nt, k8, n8, c)])[ph] = f2tf32(e[j]);
    }
}
__device__ __forceinline__ void packB32_nn(const float e[4], uint2* Bh, int tid)
{
    const int kr = tid >> 4, nc = (tid & 15) << 2;
    const int k8 = kr >> 3, c = kr & 3, ph = (kr >> 2) & 1;
    #pragma unroll
    for (int j = 0; j < 4; ++j) {
        const int n = nc + j;
        ((unsigned*)&Bh[BIDX(n >> 3, k8, n & 7, c)])[ph] = f2tf32(e[j]);
    }
}

// ---------------------------------------------------------------------------
// QKV projections (bf16x3, pipelined) -> Q/K/V in [bh, s, d]
// ---------------------------------------------------------------------------
__global__ void __launch_bounds__(256, 2)
qkv_gemm_kernel(const float* __restrict__ x,
                const float* __restrict__ Wq,
                const float* __restrict__ Wk,
                const float* __restrict__ Wv,
                int zbase)
{
    __shared__ uint4 Ah[2][256], Al[2][256];
    __shared__ uint2 Bh[2][512], Bl[2][512];

    const int z = blockIdx.z + zbase;
    const float* W = (z == 0) ? Wq : (z == 1 ? Wk : Wv);
    float*       C = (z == 0) ? g_Q : (z == 1 ? g_K : g_V);

    const int tid = threadIdx.x, lane = tid & 31, wid = tid >> 5;
    const int wm = wid >> 1, wn = wid & 1;
    const int row0 = blockIdx.y * 128, col0 = blockIdx.x * 128;
    const int r8 = lane >> 2, cc = lane & 3, cx = cc ^ (r8 & 3);
    const int lr = tid >> 1, lk = (tid & 1) << 3;

    const float* Ab = x + (size_t)(row0 + lr) * HIDDEN + lk;
    const float* Bb = W + (size_t)(col0 + lr) * HIDDEN + lk;

    float ea[8], eb[8];
    ldrow(Ab, ea); ldrow(Bb, eb);
    packA16(ea, Ah[0], Al[0], tid);
    packB16(eb, Bh[0], Bl[0], tid);
    __syncthreads();

    float d[2][8][4] = {};
    for (int k0 = 0; k0 < HIDDEN; k0 += 16) {
        const int cur = (k0 >> 4) & 1, nxt = cur ^ 1;
        const bool more = (k0 + 16) < HIDDEN;
        if (more) { ldrow(Ab + k0 + 16, ea); ldrow(Bb + k0 + 16, eb); }

        uint4 ah[2], al[2];
        #pragma unroll
        for (int mt = 0; mt < 2; ++mt) {
            ah[mt] = Ah[cur][AIDXb(wm * 2 + mt, r8, cx)];
            al[mt] = Al[cur][AIDXb(wm * 2 + mt, r8, cx)];
        }
        #pragma unroll
        for (int nt = 0; nt < 8; ++nt) {
            const int bi = BIDXb(wn * 8 + nt, r8, cc);
            const uint2 bhv = Bh[cur][bi], blv = Bl[cur][bi];
            #pragma unroll
            for (int mt = 0; mt < 2; ++mt) {
                mma16(d[mt][nt], ah[mt], bhv);
                mma16(d[mt][nt], ah[mt], blv);
                mma16(d[mt][nt], al[mt], bhv);
            }
        }
        if (more) {
            packA16(ea, Ah[nxt], Al[nxt], tid);
            packB16(eb, Bh[nxt], Bl[nxt], tid);
        }
        __syncthreads();
    }

    const int g = lane >> 2, t2 = (lane & 3) << 1;
    #pragma unroll
    for (int mt = 0; mt < 2; ++mt) {
        const int rA = row0 + (wm * 2 + mt) * 16 + g;
        const int rB = rA + 8;
        const int bA = rA >> 11, sA = rA & (SEQ - 1);
        const int bB = rB >> 11, sB = rB & (SEQ - 1);
        #pragma unroll
        for (int nt = 0; nt < 8; ++nt) {
            const int col = col0 + (wn * 8 + nt) * 8 + t2;
            const int h = col >> 6, dd = col & 63;
            *(float2*)&C[(((size_t)(bA * HEADS + h) * SEQ) + sA) * HEAD_DIM + dd] =
                make_float2(d[mt][nt][0], d[mt][nt][1]);
            *(float2*)&C[(((size_t)(bB * HEADS + h) * SEQ) + sB) * HEAD_DIM + dd] =
                make_float2(d[mt][nt][2], d[mt][nt][3]);
        }
    }
}

// ---------------------------------------------------------------------------
// Scores (bf16x3, pipelined): writes fp32 S and u16 orderable keys
// ---------------------------------------------------------------------------
__global__ void __launch_bounds__(256, 2)
scores_gemm_kernel()
{
    __shared__ uint4 Ah[2][256], Al[2][256];
    __shared__ uint2 Bh[2][512], Bl[2][512];

    const int bh = blockIdx.z;
    const float* Qb = g_Q + (size_t)bh * SEQ * HEAD_DIM;
    const float* Kb = g_K + (size_t)bh * SEQ * HEAD_DIM;
    float*       Sb = g_S + (size_t)bh * SEQ * SEQ;
    unsigned*    Kw = g_key16 + (size_t)bh * SEQ * (SEQ / 2);

    const int tid = threadIdx.x, lane = tid & 31, wid = tid >> 5;
    const int wm = wid >> 1, wn = wid & 1;
    const int row0 = blockIdx.y * 128, col0 = blockIdx.x * 128;
    const int r8 = lane >> 2, cc = lane & 3, cx = cc ^ (r8 & 3);
    const int lr = tid >> 1, lk = (tid & 1) << 3;

    const float* Ab = Qb + (size_t)(row0 + lr) * HEAD_DIM + lk;
    const float* Bb = Kb + (size_t)(col0 + lr) * HEAD_DIM + lk;

    float ea[8], eb[8];
    ldrow(Ab, ea); ldrow(Bb, eb);
    packA16(ea, Ah[0], Al[0], tid);
    packB16(eb, Bh[0], Bl[0], tid);
    __syncthreads();

    float d[2][8][4] = {};
    #pragma unroll
    for (int k0 = 0; k0 < HEAD_DIM; k0 += 16) {
        const int cur = (k0 >> 4) & 1, nxt = cur ^ 1;
        const bool more = (k0 + 16) < HEAD_DIM;
        if (more) { ldrow(Ab + k0 + 16, ea); ldrow(Bb + k0 + 16, eb); }

        uint4 ah[2], al[2];
        #pragma unroll
        for (int mt = 0; mt < 2; ++mt) {
            ah[mt] = Ah[cur][AIDXb(wm * 2 + mt, r8, cx)];
            al[mt] = Al[cur][AIDXb(wm * 2 + mt, r8, cx)];
        }
        #pragma unroll
        for (int nt = 0; nt < 8; ++nt) {
            const int bi = BIDXb(wn * 8 + nt, r8, cc);
            const uint2 bhv = Bh[cur][bi], blv = Bl[cur][bi];
            #pragma unroll
            for (int mt = 0; mt < 2; ++mt) {
                mma16(d[mt][nt], ah[mt], bhv);
                mma16(d[mt][nt], ah[mt], blv);
                mma16(d[mt][nt], al[mt], bhv);
            }
        }
        if (more) {
            packA16(ea, Ah[nxt], Al[nxt], tid);
            packB16(eb, Bh[nxt], Bl[nxt], tid);
        }
        __syncthreads();
    }

    const int g = lane >> 2, t2 = (lane & 3) << 1;
    #pragma unroll
    for (int mt = 0; mt < 2; ++mt) {
        const int qA = row0 + (wm * 2 + mt) * 16 + g;
        const int qB = qA + 8;
        #pragma unroll
        for (int nt = 0; nt < 8; ++nt) {
            const int col = col0 + (wn * 8 + nt) * 8 + t2;
            const float a0 = d[mt][nt][0] * 0.125f, a1 = d[mt][nt][1] * 0.125f;
            const float b0 = d[mt][nt][2] * 0.125f, b1 = d[mt][nt][3] * 0.125f;
            *(float2*)&Sb[(size_t)qA * SEQ + col] = make_float2(a0, a1);
            *(float2*)&Sb[(size_t)qB * SEQ + col] = make_float2(b0, b1);
            Kw[((size_t)qA * SEQ + col) >> 1] = (f2u(a0) >> 16) | ((f2u(a1) >> 16) << 16);
            Kw[((size_t)qB * SEQ + col) >> 1] = (f2u(b0) >> 16) | ((f2u(b1) >> 16) << 16);
        }
    }
}

// ---------------------------------------------------------------------------
// select16: WARP-PER-ROW 2-pass radix on u16 keys -> (kthbits, m~).
// 8 rows per CTA, fully warp-synchronous (no __syncthreads).
// ---------------------------------------------------------------------------
__global__ void __launch_bounds__(256)
select16_kernel()
{
    __shared__ unsigned hist[8][256];

    const int tid = threadIdx.x, lane = tid & 31, wrp = tid >> 5;
    const int row = blockIdx.x * 8 + wrp;
    const unsigned* Krow = g_key16 + (size_t)row * (SEQ / 2);
    unsigned* H = hist[wrp];

    // load 64 u16 keys per lane: 8 coalesced uint4 (= 256 uint4 per row)
    uint4 kv[8];
    #pragma unroll
    for (int i = 0; i < 8; ++i)
        kv[i] = ((const uint4*)Krow)[lane + (i << 5)];

    // ---- row max key ----
    unsigned mk = 0;
    #pragma unroll
    for (int i = 0; i < 8; ++i) {
        const unsigned* w = (const unsigned*)&kv[i];
        #pragma unroll
        for (int c = 0; c < 4; ++c) {
            mk = max(mk, w[c] & 0xFFFFu);
            mk = max(mk, w[c] >> 16);
        }
    }
    #pragma unroll
    for (int o = 16; o > 0; o >>= 1)
        mk = max(mk, __shfl_xor_sync(0xFFFFFFFFu, mk, o));
    const unsigned maxk = mk;   // uniform across warp

    // ---- pass 1: histogram of high byte ----
    #pragma unroll
    for (int i = 0; i < 8; ++i) H[lane + (i << 5)] = 0;
    __syncwarp();
    #pragma unroll
    for (int i = 0; i < 8; ++i) {
        const unsigned* w = (const unsigned*)&kv[i];
        #pragma unroll
        for (int c = 0; c < 4; ++c) {
            #pragma unroll
            for (int half = 0; half < 2; ++half) {
                const unsigned key = half ? (w[c] >> 16) : (w[c] & 0xFFFFu);
                const unsigned bin = key >> 8;
                const unsigned peers = __match_any_sync(0xFFFFFFFFu, bin);
                if (lane == (__ffs(peers) - 1))
                    atomicAdd(&H[bin], (unsigned)__popc(peers));
            }
        }
    }
    __syncwarp();

    // ---- scan pass 1: find b1 and residual kk ----
    unsigned b1, kk;
    {
        unsigned bc[8], tl = 0;
        #pragma unroll
        for (int j = 0; j < 8; ++j) { bc[j] = H[(lane << 3) + j]; tl += bc[j]; }
        unsigned run = tl;
        #pragma unroll
        for (int o = 1; o < 32; o <<= 1) {
            unsigned g = __shfl_down_sync(0xFFFFFFFFu, run, o);
            if (lane + o < 32) run += g;
        }
        const unsigned above = run - tl;       // sum over lanes > lane
        unsigned cum = above;
        unsigned my_b = 0xFFFFFFFFu, my_kk = 0;
        #pragma unroll
        for (int j = 7; j >= 0; --j) {
            cum += bc[j];
            if (cum >= KKEEP && (cum - bc[j]) < KKEEP) {
                my_b = (unsigned)((lane << 3) + j);
                my_kk = KKEEP - (cum - bc[j]);
            }
        }
        const unsigned msk = __ballot_sync(0xFFFFFFFFu, my_b != 0xFFFFFFFFu);
        const int src = __ffs(msk) - 1;
        b1 = __shfl_sync(0xFFFFFFFFu, my_b, src);
        kk = __shfl_sync(0xFFFFFFFFu, my_kk, src);
    }

    // ---- pass 2: histogram of low byte among keys with high byte == b1 ----
    #pragma unroll
    for (int i = 0; i < 8; ++i) H[lane + (i << 5)] = 0;
    __syncwarp();
    #pragma unroll
    for (int i = 0; i < 8; ++i) {
        const unsigned* w = (const unsigned*)&kv[i];
        #pragma unroll
        for (int c = 0; c < 4; ++c) {
            #pragma unroll
            for (int half = 0; half < 2; ++half) {
                const unsigned key = half ? (w[c] >> 16) : (w[c] & 0xFFFFu);
                const bool ok = (key >> 8) == b1;
                const unsigned mok = __ballot_sync(0xFFFFFFFFu, ok);
                if (mok) {
                    const unsigned bin = key & 0xFFu;
                    const unsigned mkey = ok ? bin : (256u + (unsigned)lane);
                    const unsigned peers = __match_any_sync(0xFFFFFFFFu, mkey);
                    if (ok && lane == (__ffs(peers) - 1))
                        atomicAdd(&H[bin], (unsigned)__popc(peers));
                }
            }
        }
    }
    __syncwarp();

    // ---- scan pass 2: find b2 ----
    unsigned b2 = 0;
    {
        unsigned bc[8], tl = 0;
        #pragma unroll
        for (int j = 0; j < 8; ++j) { bc[j] = H[(lane << 3) + j]; tl += bc[j]; }
        unsigned run = tl;
        #pragma unroll
        for (int o = 1; o < 32; o <<= 1) {
            unsigned g = __shfl_down_sync(0xFFFFFFFFu, run, o);
            if (lane + o < 32) run += g;
        }
        const unsigned above = run - tl;
        unsigned cum = above;
        unsigned my_b = 0xFFFFFFFFu;
        #pragma unroll
        for (int j = 7; j >= 0; --j) {
            cum += bc[j];
            if (cum >= kk && (cum - bc[j]) < kk)
                my_b = (unsigned)((lane << 3) + j);
        }
        const unsigned msk = __ballot_sync(0xFFFFFFFFu, my_b != 0xFFFFFFFFu);
        const int src = __ffs(msk) - 1;
        b2 = __shfl_sync(0xFFFFFFFFu, my_b, src);
    }

    if (lane == 0) {
        const unsigned kth16 = (b1 << 8) | b2;
        g_par[row] = make_float4(__uint_as_float(kth16 << 16),
                                 u2f(maxk << 16), 0.f, 0.f);
    }
}

// ---------------------------------------------------------------------------
// AV (tf32 x1, fused gate+softmax+sum, pipelined) — 256 thr
// ---------------------------------------------------------------------------
__global__ void __launch_bounds__(256, 2)
av_gemm_kernel(const float* __restrict__ thr_ptr)
{
    __shared__ uint4 Ah[2][512];
    __shared__ uint2 Bh[2][512];
    __shared__ float rowsum[128];

    const int bh   = blockIdx.y;
    const int row0 = blockIdx.x * 128;
    const float* Sb = g_S + (size_t)bh * SEQ * SEQ;
    const float* Vb = g_V + (size_t)bh * SEQ * HEAD_DIM;

    const int tid = threadIdx.x, lane = tid & 31, wid = tid >> 5;
    const int wm = wid >> 1, wn = wid & 1;
    const int r8 = lane >> 2, cc = lane & 3, cx = cc ^ (r8 & 3);
    const int lr = tid >> 1, lk = (tid & 1) << 3;
    const int kr = tid >> 4, nc = (tid & 15) << 2;

    const float4 par = g_par[(size_t)bh * SEQ + row0 + lr];
    const float thr  = fminf(fmaxf(*thr_ptr, 0.f), 1.f);
    const float gate = fmaxf(u2f(__float_as_uint(par.x)), thr);
    const float mrow = par.y;

    const float* Ab = Sb + (size_t)(row0 + lr) * SEQ + lk;
    const float* Bb = Vb + (size_t)kr * HEAD_DIM + nc;

    float psum = 0.f;
    float ea[8], evb[4];
    ldrow(Ab, ea);
    { float4 v = *(const float4*)Bb; evb[0]=v.x; evb[1]=v.y; evb[2]=v.z; evb[3]=v.w; }
    packA_av(ea, Ah[0], tid, gate, mrow, psum);
    packB32_nn(evb, Bh[0], tid);
    __syncthreads();

    float d[2][4][4] = {};
    for (int k0 = 0; k0 < SEQ; k0 += 16) {
        const int cur = (k0 >> 4) & 1, nxt = cur ^ 1;
        const bool more = (k0 + 16) < SEQ;
        if (more) {
            ldrow(Ab + k0 + 16, ea);
            float4 v = *(const float4*)(Bb + (size_t)(k0 + 16) * HEAD_DIM);
            evb[0]=v.x; evb[1]=v.y; evb[2]=v.z; evb[3]=v.w;
        }

        #pragma unroll
        for (int k8 = 0; k8 < 2; ++k8) {
            uint4 ah[2];
            #pragma unroll
            for (int mt = 0; mt < 2; ++mt)
                ah[mt] = Ah[cur][AIDX(wm * 2 + mt, k8, r8, cx)];
            #pragma unroll
            for (int nt = 0; nt < 4; ++nt) {
                const uint2 bv = Bh[cur][BIDX(wn * 4 + nt, k8, r8, cc)];
                #pragma unroll
                for (int mt = 0; mt < 2; ++mt)
                    mma8(d[mt][nt], ah[mt], bv);
            }
        }
        if (more) {
            packA_av(ea, Ah[nxt], tid, gate, mrow, psum);
            packB32_nn(evb, Bh[nxt], tid);
        }
        __syncthreads();
    }

    {
        const float tot = psum + __shfl_xor_sync(0xFFFFFFFFu, psum, 1);
        if ((tid & 1) == 0) rowsum[lr] = tot;
    }
    __syncthreads();

    const int b = bh >> 4, h = bh & 15;
    const int g = lane >> 2, t2 = (lane & 3) << 1;
    #pragma unroll
    for (int mt = 0; mt < 2; ++mt) {
        const int qA = row0 + (wm * 2 + mt) * 16 + g;
        const int qB = qA + 8;
        const float invA = 1.f / rowsum[qA - row0];
        const float invB = 1.f / rowsum[qB - row0];
        #pragma unroll
        for (int nt = 0; nt < 4; ++nt) {
            const int col = (wn * 4 + nt) * 8 + t2;
            *(float2*)&g_O[(((size_t)b * SEQ + qA) * HIDDEN) + h * HEAD_DIM + col] =
                make_float2(d[mt][nt][0] * invA, d[mt][nt][1] * invA);
            *(float2*)&g_O[(((size_t)b * SEQ + qB) * HIDDEN) + h * HEAD_DIM + col] =
                make_float2(d[mt][nt][2] * invB, d[mt][nt][3] * invB);
        }
    }
}

// ---------------------------------------------------------------------------
// Output projection (tf32 x1, pipelined): Y = g_O @ Wo^T + bo
// ---------------------------------------------------------------------------
__global__ void __launch_bounds__(256, 2)
out_gemm_kernel(const float* __restrict__ Wo,
                const float* __restrict__ bo,
                float* __restrict__ Y)
{
    __shared__ uint4 Ah[2][512];
    __shared__ uint2 Bh[2][1024];

    const int tid = threadIdx.x, lane = tid & 31, wid = tid >> 5;
    const int wm = wid >> 1, wn = wid & 1;
    const int row0 = blockIdx.y * 128, col0 = blockIdx.x * 128;
    const int r8 = lane >> 2, cc = lane & 3, cx = cc ^ (r8 & 3);
    const int lr = tid >> 1, lk = (tid & 1) << 3;

    const float* Ab = g_O + (size_t)(row0 + lr) * HIDDEN + lk;
    const float* Bb = Wo  + (size_t)(col0 + lr) * HIDDEN + lk;

    float ea[8], eb[8];
    ldrow(Ab, ea); ldrow(Bb, eb);
    packA32(ea, Ah[0], tid);
    packB32_nt(eb, Bh[0], tid);
    __syncthreads();

    float d[2][8][4] = {};
    for (int k0 = 0; k0 < HIDDEN; k0 += 16) {
        const int cur = (k0 >> 4) & 1, nxt = cur ^ 1;
        const bool more = (k0 + 16) < HIDDEN;
        if (more) { ldrow(Ab + k0 + 16, ea); ldrow(Bb + k0 + 16, eb); }

        #pragma unroll
        for (int k8 = 0; k8 < 2; ++k8) {
            uint4 ah[2];
            #pragma unroll
            for (int mt = 0; mt < 2; ++mt)
                ah[mt] = Ah[cur][AIDX(wm * 2 + mt, k8, r8, cx)];
            #pragma unroll
            for (int nt = 0; nt < 8; ++nt) {
                const uint2 bv = Bh[cur][BIDX(wn * 8 + nt, k8, r8, cc)];
                #pragma unroll
                for (int mt = 0; mt < 2; ++mt)
                    mma8(d[mt][nt], ah[mt], bv);
            }
        }
        if (more) {
            packA32(ea, Ah[nxt], tid);
            packB32_nt(eb, Bh[nxt], tid);
        }
        __syncthreads();
    }

    const int g = lane >> 2, t2 = (lane & 3) << 1;
    #pragma unroll
    for (int mt = 0; mt < 2; ++mt) {
        const int rA = row0 + (wm * 2 + mt) * 16 + g;
        const int rB = rA + 8;
        #pragma unroll
        for (int nt = 0; nt < 8; ++nt) {
            const int col = col0 + (wn * 8 + nt) * 8 + t2;
            const float b0 = bo[col], b1 = bo[col + 1];
            *(float2*)&Y[(size_t)rA * HIDDEN + col] =
                make_float2(d[mt][nt][0] + b0, d[mt][nt][1] + b1);
            *(float2*)&Y[(size_t)rB * HIDDEN + col] =
                make_float2(d[mt][nt][2] + b0, d[mt][nt][3] + b1);
        }
    }
}

// ---------------------------------------------------------------------------
extern "C" void kernel_launch(void* const* d_in, const int* in_sizes, int n_in,
                              void* d_out, int out_size)
{
    const float* x   = (const float*)d_in[0];
    const float* Wq  = (const float*)d_in[1];
    const float* Wk  = (const float*)d_in[2];
    const float* Wv  = (const float*)d_in[3];
    const float* Wo  = (const float*)d_in[4];
    const float* bo  = (const float*)d_in[5];
    const float* thr = (const float*)d_in[6];
    float* out = (float*)d_out;

    static cudaStream_t s_v = nullptr;
    static cudaEvent_t  ev_fork = nullptr, ev_join = nullptr;
    if (s_v == nullptr) {
        cudaStreamCreateWithFlags(&s_v, cudaStreamNonBlocking);
        cudaEventCreateWithFlags(&ev_fork, cudaEventDisableTiming);
        cudaEventCreateWithFlags(&ev_join, cudaEventDisableTiming);
    }

    cudaEventRecord(ev_fork, 0);
    cudaStreamWaitEvent(s_v, ev_fork, 0);

    // V projection overlaps scores+select on the side stream
    dim3 gv(HIDDEN / 128, MROWS / 128, 1);
    qkv_gemm_kernel<<<gv, 256, 0, s_v>>>(x, Wq, Wk, Wv, 2);

    dim3 gqk(HIDDEN / 128, MROWS / 128, 2);
    qkv_gemm_kernel<<<gqk, 256>>>(x, Wq, Wk, Wv, 0);

    dim3 gs(SEQ / 128, SEQ / 128, BH);
    scores_gemm_kernel<<<gs, 256>>>();

    select16_kernel<<<BH * SEQ / 8, 256>>>();

    cudaEventRecord(ev_join, s_v);
    cudaStreamWaitEvent(0, ev_join, 0);

    dim3 gav(SEQ / 128, BH);
    av_gemm_kernel<<<gav, 256>>>(thr);

    dim3 go(HIDDEN / 128, MROWS / 128);
    out_gemm_kernel<<<go, 256>>>(Wo, bo, out);
}

// round 10
// speedup vs baseline: 1.3367x; 1.3367x over previous
#include <cuda_runtime.h>
#include <cuda_bf16.h>
#include <math.h>

#define HIDDEN   1024
#define HEADS    16
#define HEAD_DIM 64
#define BATCH    2
#define SEQ      2048
#define MROWS    (BATCH*SEQ)     // 4096
#define BH       (BATCH*HEADS)   // 32
#define KKEEP    1024

// ---------------------------------------------------------------------------
// Scratch (device globals; no runtime allocation allowed)
// ---------------------------------------------------------------------------
__device__ float    g_Q[(size_t)BH*SEQ*HEAD_DIM];
__device__ float    g_K[(size_t)BH*SEQ*HEAD_DIM];
__device__ float    g_V[(size_t)BH*SEQ*HEAD_DIM];
__device__ float    g_O[(size_t)MROWS*HIDDEN];
__device__ float    g_S[(size_t)BH*SEQ*SEQ];            // fp32 scores, 512MB
__device__ unsigned g_key16[(size_t)BH*SEQ*SEQ/2];      // u16 orderable keys
__device__ float4   g_par[(size_t)BH*SEQ];              // (kthbits, m~, 0, 0)

// ---------------------------------------------------------------------------
// MMA plumbing
// ---------------------------------------------------------------------------
__device__ __forceinline__ unsigned f2tf32(float f) {
    unsigned u;
    asm("cvt.rna.tf32.f32 %0, %1;" : "=r"(u) : "f"(f));
    return u;
}
__device__ __forceinline__ void mma8(float d[4], const uint4& a, const uint2& b) {
    asm("mma.sync.aligned.m16n8k8.row.col.f32.tf32.tf32.f32 "
        "{%0,%1,%2,%3},{%4,%5,%6,%7},{%8,%9},{%0,%1,%2,%3};"
        : "+f"(d[0]), "+f"(d[1]), "+f"(d[2]), "+f"(d[3])
        : "r"(a.x), "r"(a.y), "r"(a.z), "r"(a.w), "r"(b.x), "r"(b.y));
}
__device__ __forceinline__ void mma16(float d[4], const uint4& a, const uint2& b) {
    asm("mma.sync.aligned.m16n8k16.row.col.f32.bf16.bf16.f32 "
        "{%0,%1,%2,%3},{%4,%5,%6,%7},{%8,%9},{%0,%1,%2,%3};"
        : "+f"(d[0]), "+f"(d[1]), "+f"(d[2]), "+f"(d[3])
        : "r"(a.x), "r"(a.y), "r"(a.z), "r"(a.w), "r"(b.x), "r"(b.y));
}

// tf32 frag indexers (k8 granularity, 2 k8 per chunk16)
__device__ __forceinline__ int AIDX(int mt, int k8, int r8, int cx) {
    return ((((mt << 1) + k8) << 3) + r8) * 4 + cx;
}
__device__ __forceinline__ int BIDX(int nt, int k8, int n8, int c) {
    return ((((nt << 1) + k8) << 3) + n8) * 4 + c;
}
// bf16 frag indexers (k16 granularity)
__device__ __forceinline__ int AIDXb(int mt, int r8, int cx) {
    return ((mt << 3) + r8) * 4 + cx;
}
__device__ __forceinline__ int BIDXb(int nt, int n8, int c) {
    return ((nt << 3) + n8) * 4 + c;
}

__device__ __forceinline__ void ldrow(const float* __restrict__ p, float e[8]) {
    float4 a = *(const float4*)p;
    float4 b = *(const float4*)(p + 4);
    e[0]=a.x; e[1]=a.y; e[2]=a.z; e[3]=a.w;
    e[4]=b.x; e[5]=b.y; e[6]=b.z; e[7]=b.w;
}

__device__ __forceinline__ void bsplit(float e, unsigned short& h, unsigned short& l) {
    __nv_bfloat16 bh = __float2bfloat16(e);
    h = __bfloat16_as_ushort(bh);
    l = __bfloat16_as_ushort(__float2bfloat16(e - __bfloat162float(bh)));
}

// ---- bf16 packs (hi + lo) ----
__device__ __forceinline__ void packA16(const float e[8], uint4* Ah, uint4* Al, int tid)
{
    const int lr = tid >> 1, kh = tid & 1;
    const int mt = lr >> 4, rr = lr & 15, r8 = rr & 7, rh = rr >> 3;
    const int comp = rh + (kh << 1);
    #pragma unroll
    for (int c = 0; c < 4; ++c) {
        unsigned short h0, l0, h1, l1;
        bsplit(e[2*c],   h0, l0);
        bsplit(e[2*c+1], h1, l1);
        const int idx = AIDXb(mt, r8, c ^ (r8 & 3));
        ((unsigned*)&Ah[idx])[comp] = (unsigned)h0 | ((unsigned)h1 << 16);
        ((unsigned*)&Al[idx])[comp] = (unsigned)l0 | ((unsigned)l1 << 16);
    }
}
__device__ __forceinline__ void packB16(const float e[8], uint2* Bh, uint2* Bl, int tid)
{
    const int ln = tid >> 1, kh = tid & 1;
    const int nt = ln >> 3, n8 = ln & 7;
    #pragma unroll
    for (int c = 0; c < 4; ++c) {
        unsigned short h0, l0, h1, l1;
        bsplit(e[2*c],   h0, l0);
        bsplit(e[2*c+1], h1, l1);
        const int idx = BIDXb(nt, n8, c);
        ((unsigned*)&Bh[idx])[kh] = (unsigned)h0 | ((unsigned)h1 << 16);
        ((unsigned*)&Bl[idx])[kh] = (unsigned)l0 | ((unsigned)l1 << 16);
    }
}

// ---- tf32 packs ----
__device__ __forceinline__ void packA32(const float e[8], uint4* Ah, int tid)
{
    const int lr = tid >> 1;
    const int mt = lr >> 4, rr = lr & 15, r8 = rr & 7, rh = rr >> 3, k8 = tid & 1;
    #pragma unroll
    for (int j = 0; j < 8; ++j) {
        const int c = j & 3, ch = (j >> 2) & 1;
        const int comp = rh + (ch << 1);
        ((unsigned*)&Ah[AIDX(mt, k8, r8, c ^ (r8 & 3))])[comp] = f2tf32(e[j]);
    }
}
__device__ __forceinline__ unsigned f2u(float f) {
    unsigned b = __float_as_uint(f);
    return (b & 0x80000000u) ? ~b : (b | 0x80000000u);
}
__device__ __forceinline__ float u2f(unsigned u) {
    unsigned b = (u & 0x80000000u) ? (u & 0x7FFFFFFFu) : ~u;
    return __uint_as_float(b);
}
// gate is a plain fp32 threshold: keep iff s >= gate
__device__ __forceinline__ void packA_av(const float e[8], uint4* Ah, int tid,
                                         float gate, float m, float& psum)
{
    const int lr = tid >> 1;
    const int mt = lr >> 4, rr = lr & 15, r8 = rr & 7, rh = rr >> 3, k8 = tid & 1;
    #pragma unroll
    for (int j = 0; j < 8; ++j) {
        const float pe = (e[j] >= gate) ? __expf(e[j] - m) : 0.f;
        psum += pe;
        const int c = j & 3, ch = (j >> 2) & 1;
        const int comp = rh + (ch << 1);
        ((unsigned*)&Ah[AIDX(mt, k8, r8, c ^ (r8 & 3))])[comp] = f2tf32(pe);
    }
}
__device__ __forceinline__ void packB32_nt(const float e[8], uint2* Bh, int tid)
{
    const int ln = tid >> 1;
    const int nt = ln >> 3, n8 = ln & 7, k8 = tid & 1;
    #pragma unroll
    for (int j = 0; j < 8; ++j) {
        const int c = j & 3, ph = (j >> 2) & 1;
        ((unsigned*)&Bh[BIDX(nt, k8, n8, c)])[ph] = f2tf32(e[j]);
    }
}
__device__ __forceinline__ void packB32_nn(const float e[4], uint2* Bh, int tid)
{
    const int kr = tid >> 4, nc = (tid & 15) << 2;
    const int k8 = kr >> 3, c = kr & 3, ph = (kr >> 2) & 1;
    #pragma unroll
    for (int j = 0; j < 4; ++j) {
        const int n = nc + j;
        ((unsigned*)&Bh[BIDX(n >> 3, k8, n & 7, c)])[ph] = f2tf32(e[j]);
    }
}

// ---------------------------------------------------------------------------
// QKV projections (bf16x3, pipelined) -> Q/K/V in [bh, s, d]
// ---------------------------------------------------------------------------
__global__ void __launch_bounds__(256, 2)
qkv_gemm_kernel(const float* __restrict__ x,
                const float* __restrict__ Wq,
                const float* __restrict__ Wk,
                const float* __restrict__ Wv,
                int zbase)
{
    __shared__ uint4 Ah[2][256], Al[2][256];
    __shared__ uint2 Bh[2][512], Bl[2][512];

    const int z = blockIdx.z + zbase;
    const float* W = (z == 0) ? Wq : (z == 1 ? Wk : Wv);
    float*       C = (z == 0) ? g_Q : (z == 1 ? g_K : g_V);

    const int tid = threadIdx.x, lane = tid & 31, wid = tid >> 5;
    const int wm = wid >> 1, wn = wid & 1;
    const int row0 = blockIdx.y * 128, col0 = blockIdx.x * 128;
    const int r8 = lane >> 2, cc = lane & 3, cx = cc ^ (r8 & 3);
    const int lr = tid >> 1, lk = (tid & 1) << 3;

    const float* Ab = x + (size_t)(row0 + lr) * HIDDEN + lk;
    const float* Bb = W + (size_t)(col0 + lr) * HIDDEN + lk;

    float ea[8], eb[8];
    ldrow(Ab, ea); ldrow(Bb, eb);
    packA16(ea, Ah[0], Al[0], tid);
    packB16(eb, Bh[0], Bl[0], tid);
    __syncthreads();

    float d[2][8][4] = {};
    for (int k0 = 0; k0 < HIDDEN; k0 += 16) {
        const int cur = (k0 >> 4) & 1, nxt = cur ^ 1;
        const bool more = (k0 + 16) < HIDDEN;
        if (more) { ldrow(Ab + k0 + 16, ea); ldrow(Bb + k0 + 16, eb); }

        uint4 ah[2], al[2];
        #pragma unroll
        for (int mt = 0; mt < 2; ++mt) {
            ah[mt] = Ah[cur][AIDXb(wm * 2 + mt, r8, cx)];
            al[mt] = Al[cur][AIDXb(wm * 2 + mt, r8, cx)];
        }
        #pragma unroll
        for (int nt = 0; nt < 8; ++nt) {
            const int bi = BIDXb(wn * 8 + nt, r8, cc);
            const uint2 bhv = Bh[cur][bi], blv = Bl[cur][bi];
            #pragma unroll
            for (int mt = 0; mt < 2; ++mt) {
                mma16(d[mt][nt], ah[mt], bhv);
                mma16(d[mt][nt], ah[mt], blv);
                mma16(d[mt][nt], al[mt], bhv);
            }
        }
        if (more) {
            packA16(ea, Ah[nxt], Al[nxt], tid);
            packB16(eb, Bh[nxt], Bl[nxt], tid);
        }
        __syncthreads();
    }

    const int g = lane >> 2, t2 = (lane & 3) << 1;
    #pragma unroll
    for (int mt = 0; mt < 2; ++mt) {
        const int rA = row0 + (wm * 2 + mt) * 16 + g;
        const int rB = rA + 8;
        const int bA = rA >> 11, sA = rA & (SEQ - 1);
        const int bB = rB >> 11, sB = rB & (SEQ - 1);
        #pragma unroll
        for (int nt = 0; nt < 8; ++nt) {
            const int col = col0 + (wn * 8 + nt) * 8 + t2;
            const int h = col >> 6, dd = col & 63;
            *(float2*)&C[(((size_t)(bA * HEADS + h) * SEQ) + sA) * HEAD_DIM + dd] =
                make_float2(d[mt][nt][0], d[mt][nt][1]);
            *(float2*)&C[(((size_t)(bB * HEADS + h) * SEQ) + sB) * HEAD_DIM + dd] =
                make_float2(d[mt][nt][2], d[mt][nt][3]);
        }
    }
}

// ---------------------------------------------------------------------------
// Scores (bf16x3, pipelined): writes fp32 S and u16 orderable keys
// bh = blockIdx.z + bh_base (for split-stream pipelining)
// ---------------------------------------------------------------------------
__global__ void __launch_bounds__(256, 2)
scores_gemm_kernel(int bh_base)
{
    __shared__ uint4 Ah[2][256], Al[2][256];
    __shared__ uint2 Bh[2][512], Bl[2][512];

    const int bh = blockIdx.z + bh_base;
    const float* Qb = g_Q + (size_t)bh * SEQ * HEAD_DIM;
    const float* Kb = g_K + (size_t)bh * SEQ * HEAD_DIM;
    float*       Sb = g_S + (size_t)bh * SEQ * SEQ;
    unsigned*    Kw = g_key16 + (size_t)bh * SEQ * (SEQ / 2);

    const int tid = threadIdx.x, lane = tid & 31, wid = tid >> 5;
    const int wm = wid >> 1, wn = wid & 1;
    const int row0 = blockIdx.y * 128, col0 = blockIdx.x * 128;
    const int r8 = lane >> 2, cc = lane & 3, cx = cc ^ (r8 & 3);
    const int lr = tid >> 1, lk = (tid & 1) << 3;

    const float* Ab = Qb + (size_t)(row0 + lr) * HEAD_DIM + lk;
    const float* Bb = Kb + (size_t)(col0 + lr) * HEAD_DIM + lk;

    float ea[8], eb[8];
    ldrow(Ab, ea); ldrow(Bb, eb);
    packA16(ea, Ah[0], Al[0], tid);
    packB16(eb, Bh[0], Bl[0], tid);
    __syncthreads();

    float d[2][8][4] = {};
    #pragma unroll
    for (int k0 = 0; k0 < HEAD_DIM; k0 += 16) {
        const int cur = (k0 >> 4) & 1, nxt = cur ^ 1;
        const bool more = (k0 + 16) < HEAD_DIM;
        if (more) { ldrow(Ab + k0 + 16, ea); ldrow(Bb + k0 + 16, eb); }

        uint4 ah[2], al[2];
        #pragma unroll
        for (int mt = 0; mt < 2; ++mt) {
            ah[mt] = Ah[cur][AIDXb(wm * 2 + mt, r8, cx)];
            al[mt] = Al[cur][AIDXb(wm * 2 + mt, r8, cx)];
        }
        #pragma unroll
        for (int nt = 0; nt < 8; ++nt) {
            const int bi = BIDXb(wn * 8 + nt, r8, cc);
            const uint2 bhv = Bh[cur][bi], blv = Bl[cur][bi];
            #pragma unroll
            for (int mt = 0; mt < 2; ++mt) {
                mma16(d[mt][nt], ah[mt], bhv);
                mma16(d[mt][nt], ah[mt], blv);
                mma16(d[mt][nt], al[mt], bhv);
            }
        }
        if (more) {
            packA16(ea, Ah[nxt], Al[nxt], tid);
            packB16(eb, Bh[nxt], Bl[nxt], tid);
        }
        __syncthreads();
    }

    const int g = lane >> 2, t2 = (lane & 3) << 1;
    #pragma unroll
    for (int mt = 0; mt < 2; ++mt) {
        const int qA = row0 + (wm * 2 + mt) * 16 + g;
        const int qB = qA + 8;
        #pragma unroll
        for (int nt = 0; nt < 8; ++nt) {
            const int col = col0 + (wn * 8 + nt) * 8 + t2;
            const float a0 = d[mt][nt][0] * 0.125f, a1 = d[mt][nt][1] * 0.125f;
            const float b0 = d[mt][nt][2] * 0.125f, b1 = d[mt][nt][3] * 0.125f;
            *(float2*)&Sb[(size_t)qA * SEQ + col] = make_float2(a0, a1);
            *(float2*)&Sb[(size_t)qB * SEQ + col] = make_float2(b0, b1);
            Kw[((size_t)qA * SEQ + col) >> 1] = (f2u(a0) >> 16) | ((f2u(a1) >> 16) << 16);
            Kw[((size_t)qB * SEQ + col) >> 1] = (f2u(b0) >> 16) | ((f2u(b1) >> 16) << 16);
        }
    }
}

// ---------------------------------------------------------------------------
// select16: block-per-row 2-pass radix on u16 keys (round-8 proven version)
// row = blockIdx.x + row_base
// ---------------------------------------------------------------------------
__global__ void select16_kernel(int row_base)
{
    const int tid = threadIdx.x;
    const int row = blockIdx.x + row_base;
    const unsigned* Krow = g_key16 + (size_t)row * (SEQ / 2);

    __shared__ unsigned hist[256];
    __shared__ unsigned wsum[8];
    __shared__ unsigned s_b;
    __shared__ int      s_kk;
    __shared__ unsigned s_max;

    uint4 kv = ((const uint4*)Krow)[tid];   // 8 u16 keys
    unsigned k[8] = { kv.x & 0xFFFFu, kv.x >> 16, kv.y & 0xFFFFu, kv.y >> 16,
                      kv.z & 0xFFFFu, kv.z >> 16, kv.w & 0xFFFFu, kv.w >> 16 };

    const int lane = tid & 31, wrp = tid >> 5;

    // ---- row max key ----
    unsigned mk = k[0];
    #pragma unroll
    for (int t = 1; t < 8; ++t) mk = max(mk, k[t]);
    #pragma unroll
    for (int o = 16; o > 0; o >>= 1) mk = max(mk, __shfl_xor_sync(0xFFFFFFFFu, mk, o));
    if (lane == 0) wsum[wrp] = mk;
    __syncthreads();
    if (tid == 0) {
        unsigned m0 = wsum[0];
        #pragma unroll
        for (int w = 1; w < 8; ++w) m0 = max(m0, wsum[w]);
        s_max = m0;
    }
    __syncthreads();
    const unsigned maxk = s_max;

    // ---- pass 1 (high byte) ----
    int kk = KKEEP;
    unsigned b1;
    hist[tid] = 0;
    __syncthreads();
    #pragma unroll
    for (int t = 0; t < 8; ++t) {
        const unsigned bin = k[t] >> 8;
        const unsigned peers = __match_any_sync(0xFFFFFFFFu, bin);
        if (lane == (__ffs(peers) - 1))
            atomicAdd(&hist[bin], (unsigned)__popc(peers));
    }
    __syncthreads();
    {
        unsigned myc = hist[tid];
        unsigned cum = myc;
        #pragma unroll
        for (int o = 1; o < 32; o <<= 1) {
            unsigned g2 = __shfl_down_sync(0xFFFFFFFFu, cum, o);
            if (lane + o < 32) cum += g2;
        }
        if (lane == 0) wsum[wrp] = cum;
        __syncthreads();
        unsigned above = 0;
        #pragma unroll
        for (int w = 0; w < 8; ++w) if (w > wrp) above += wsum[w];
        cum += above;
        if (cum >= (unsigned)kk && (cum - myc) < (unsigned)kk) {
            s_b  = (unsigned)tid;
            s_kk = kk - (int)(cum - myc);
        }
    }
    __syncthreads();
    b1 = s_b;
    kk = s_kk;
    __syncthreads();

    // ---- pass 2 (low byte, among prefix matches) ----
    hist[tid] = 0;
    __syncthreads();
    #pragma unroll
    for (int t = 0; t < 8; ++t) {
        const bool ok = (k[t] >> 8) == b1;
        const unsigned mok = __ballot_sync(0xFFFFFFFFu, ok);
        if (mok) {
            const unsigned bin = k[t] & 0xFFu;
            const unsigned key = ok ? bin : (256u + (unsigned)lane);
            const unsigned peers = __match_any_sync(0xFFFFFFFFu, key);
            if (ok && lane == (__ffs(peers) - 1))
                atomicAdd(&hist[bin], (unsigned)__popc(peers));
        }
    }
    __syncthreads();
    {
        unsigned myc = hist[tid];
        unsigned cum = myc;
        #pragma unroll
        for (int o = 1; o < 32; o <<= 1) {
            unsigned g2 = __shfl_down_sync(0xFFFFFFFFu, cum, o);
            if (lane + o < 32) cum += g2;
        }
        if (lane == 0) wsum[wrp] = cum;
        __syncthreads();
        unsigned above = 0;
        #pragma unroll
        for (int w = 0; w < 8; ++w) if (w > wrp) above += wsum[w];
        cum += above;
        if (cum >= (unsigned)kk && (cum - myc) < (unsigned)kk)
            s_b = (b1 << 8) | (unsigned)tid;
    }
    __syncthreads();

    if (tid == 0) {
        const unsigned kth16 = s_b;
        g_par[row] = make_float4(__uint_as_float(kth16 << 16),
                                 u2f(maxk << 16), 0.f, 0.f);
    }
}

// ---------------------------------------------------------------------------
// AV (tf32 x1, fused gate+softmax+sum, pipelined) — 256 thr
// bh = blockIdx.y + bh_base
// ---------------------------------------------------------------------------
__global__ void __launch_bounds__(256, 2)
av_gemm_kernel(const float* __restrict__ thr_ptr, int bh_base)
{
    __shared__ uint4 Ah[2][512];
    __shared__ uint2 Bh[2][512];
    __shared__ float rowsum[128];

    const int bh   = blockIdx.y + bh_base;
    const int row0 = blockIdx.x * 128;
    const float* Sb = g_S + (size_t)bh * SEQ * SEQ;
    const float* Vb = g_V + (size_t)bh * SEQ * HEAD_DIM;

    const int tid = threadIdx.x, lane = tid & 31, wid = tid >> 5;
    const int wm = wid >> 1, wn = wid & 1;
    const int r8 = lane >> 2, cc = lane & 3, cx = cc ^ (r8 & 3);
    const int lr = tid >> 1, lk = (tid & 1) << 3;
    const int kr = tid >> 4, nc = (tid & 15) << 2;

    const float4 par = g_par[(size_t)bh * SEQ + row0 + lr];
    const float thr  = fminf(fmaxf(*thr_ptr, 0.f), 1.f);
    const float gate = fmaxf(u2f(__float_as_uint(par.x)), thr);
    const float mrow = par.y;

    const float* Ab = Sb + (size_t)(row0 + lr) * SEQ + lk;
    const float* Bb = Vb + (size_t)kr * HEAD_DIM + nc;

    float psum = 0.f;
    float ea[8], evb[4];
    ldrow(Ab, ea);
    { float4 v = *(const float4*)Bb; evb[0]=v.x; evb[1]=v.y; evb[2]=v.z; evb[3]=v.w; }
    packA_av(ea, Ah[0], tid, gate, mrow, psum);
    packB32_nn(evb, Bh[0], tid);
    __syncthreads();

    float d[2][4][4] = {};
    for (int k0 = 0; k0 < SEQ; k0 += 16) {
        const int cur = (k0 >> 4) & 1, nxt = cur ^ 1;
        const bool more = (k0 + 16) < SEQ;
        if (more) {
            ldrow(Ab + k0 + 16, ea);
            float4 v = *(const float4*)(Bb + (size_t)(k0 + 16) * HEAD_DIM);
            evb[0]=v.x; evb[1]=v.y; evb[2]=v.z; evb[3]=v.w;
        }

        #pragma unroll
        for (int k8 = 0; k8 < 2; ++k8) {
            uint4 ah[2];
            #pragma unroll
            for (int mt = 0; mt < 2; ++mt)
                ah[mt] = Ah[cur][AIDX(wm * 2 + mt, k8, r8, cx)];
            #pragma unroll
            for (int nt = 0; nt < 4; ++nt) {
                const uint2 bv = Bh[cur][BIDX(wn * 4 + nt, k8, r8, cc)];
                #pragma unroll
                for (int mt = 0; mt < 2; ++mt)
                    mma8(d[mt][nt], ah[mt], bv);
            }
        }
        if (more) {
            packA_av(ea, Ah[nxt], tid, gate, mrow, psum);
            packB32_nn(evb, Bh[nxt], tid);
        }
        __syncthreads();
    }

    {
        const float tot = psum + __shfl_xor_sync(0xFFFFFFFFu, psum, 1);
        if ((tid & 1) == 0) rowsum[lr] = tot;
    }
    __syncthreads();

    const int b = bh >> 4, h = bh & 15;
    const int g = lane >> 2, t2 = (lane & 3) << 1;
    #pragma unroll
    for (int mt = 0; mt < 2; ++mt) {
        const int qA = row0 + (wm * 2 + mt) * 16 + g;
        const int qB = qA + 8;
        const float invA = 1.f / rowsum[qA - row0];
        const float invB = 1.f / rowsum[qB - row0];
        #pragma unroll
        for (int nt = 0; nt < 4; ++nt) {
            const int col = (wn * 4 + nt) * 8 + t2;
            *(float2*)&g_O[(((size_t)b * SEQ + qA) * HIDDEN) + h * HEAD_DIM + col] =
                make_float2(d[mt][nt][0] * invA, d[mt][nt][1] * invA);
            *(float2*)&g_O[(((size_t)b * SEQ + qB) * HIDDEN) + h * HEAD_DIM + col] =
                make_float2(d[mt][nt][2] * invB, d[mt][nt][3] * invB);
        }
    }
}

// ---------------------------------------------------------------------------
// Output projection (tf32 x1, pipelined): Y = g_O @ Wo^T + bo
// ---------------------------------------------------------------------------
__global__ void __launch_bounds__(256, 2)
out_gemm_kernel(const float* __restrict__ Wo,
                const float* __restrict__ bo,
                float* __restrict__ Y)
{
    __shared__ uint4 Ah[2][512];
    __shared__ uint2 Bh[2][1024];

    const int tid = threadIdx.x, lane = tid & 31, wid = tid >> 5;
    const int wm = wid >> 1, wn = wid & 1;
    const int row0 = blockIdx.y * 128, col0 = blockIdx.x * 128;
    const int r8 = lane >> 2, cc = lane & 3, cx = cc ^ (r8 & 3);
    const int lr = tid >> 1, lk = (tid & 1) << 3;

    const float* Ab = g_O + (size_t)(row0 + lr) * HIDDEN + lk;
    const float* Bb = Wo  + (size_t)(col0 + lr) * HIDDEN + lk;

    float ea[8], eb[8];
    ldrow(Ab, ea); ldrow(Bb, eb);
    packA32(ea, Ah[0], tid);
    packB32_nt(eb, Bh[0], tid);
    __syncthreads();

    float d[2][8][4] = {};
    for (int k0 = 0; k0 < HIDDEN; k0 += 16) {
        const int cur = (k0 >> 4) & 1, nxt = cur ^ 1;
        const bool more = (k0 + 16) < HIDDEN;
        if (more) { ldrow(Ab + k0 + 16, ea); ldrow(Bb + k0 + 16, eb); }

        #pragma unroll
        for (int k8 = 0; k8 < 2; ++k8) {
            uint4 ah[2];
            #pragma unroll
            for (int mt = 0; mt < 2; ++mt)
                ah[mt] = Ah[cur][AIDX(wm * 2 + mt, k8, r8, cx)];
            #pragma unroll
            for (int nt = 0; nt < 8; ++nt) {
                const uint2 bv = Bh[cur][BIDX(wn * 8 + nt, k8, r8, cc)];
                #pragma unroll
                for (int mt = 0; mt < 2; ++mt)
                    mma8(d[mt][nt], ah[mt], bv);
            }
        }
        if (more) {
            packA32(ea, Ah[nxt], tid);
            packB32_nt(eb, Bh[nxt], tid);
        }
        __syncthreads();
    }

    const int g = lane >> 2, t2 = (lane & 3) << 1;
    #pragma unroll
    for (int mt = 0; mt < 2; ++mt) {
        const int rA = row0 + (wm * 2 + mt) * 16 + g;
        const int rB = rA + 8;
        #pragma unroll
        for (int nt = 0; nt < 8; ++nt) {
            const int col = col0 + (wn * 8 + nt) * 8 + t2;
            const float b0 = bo[col], b1 = bo[col + 1];
            *(float2*)&Y[(size_t)rA * HIDDEN + col] =
                make_float2(d[mt][nt][0] + b0, d[mt][nt][1] + b1);
            *(float2*)&Y[(size_t)rB * HIDDEN + col] =
                make_float2(d[mt][nt][2] + b0, d[mt][nt][3] + b1);
        }
    }
}

// ---------------------------------------------------------------------------
// Launch: V projection on side stream s_v; scores->select->av split into two
// bh-halves, half B pipelined on stream s_b so select(B) overlaps av(A) and
// scores(B) overlaps select(A). All resources created once outside capture.
// ---------------------------------------------------------------------------
extern "C" void kernel_launch(void* const* d_in, const int* in_sizes, int n_in,
                              void* d_out, int out_size)
{
    const float* x   = (const float*)d_in[0];
    const float* Wq  = (const float*)d_in[1];
    const float* Wk  = (const float*)d_in[2];
    const float* Wv  = (const float*)d_in[3];
    const float* Wo  = (const float*)d_in[4];
    const float* bo  = (const float*)d_in[5];
    const float* thr = (const float*)d_in[6];
    float* out = (float*)d_out;

    static cudaStream_t s_v = nullptr, s_b = nullptr;
    static cudaEvent_t  ev_fork = nullptr, ev_v = nullptr,
                        ev_qk = nullptr, ev_b = nullptr;
    if (s_v == nullptr) {
        cudaStreamCreateWithFlags(&s_v, cudaStreamNonBlocking);
        cudaStreamCreateWithFlags(&s_b, cudaStreamNonBlocking);
        cudaEventCreateWithFlags(&ev_fork, cudaEventDisableTiming);
        cudaEventCreateWithFlags(&ev_v,    cudaEventDisableTiming);
        cudaEventCreateWithFlags(&ev_qk,   cudaEventDisableTiming);
        cudaEventCreateWithFlags(&ev_b,    cudaEventDisableTiming);
    }

    const int HB = BH / 2;   // 16 heads per half

    // fork side streams
    cudaEventRecord(ev_fork, 0);
    cudaStreamWaitEvent(s_v, ev_fork, 0);

    // V projection on s_v
    dim3 gv(HIDDEN / 128, MROWS / 128, 1);
    qkv_gemm_kernel<<<gv, 256, 0, s_v>>>(x, Wq, Wk, Wv, 2);
    cudaEventRecord(ev_v, s_v);

    // Q,K projections on main
    dim3 gqk(HIDDEN / 128, MROWS / 128, 2);
    qkv_gemm_kernel<<<gqk, 256>>>(x, Wq, Wk, Wv, 0);
    cudaEventRecord(ev_qk, 0);

    // ---- half B chain on s_b ----
    cudaStreamWaitEvent(s_b, ev_qk, 0);
    dim3 gs(SEQ / 128, SEQ / 128, HB);
    scores_gemm_kernel<<<gs, 256, 0, s_b>>>(HB);
    select16_kernel<<<HB * SEQ, 256, 0, s_b>>>(HB * SEQ);
    cudaStreamWaitEvent(s_b, ev_v, 0);
    dim3 gav(SEQ / 128, HB);
    av_gemm_kernel<<<gav, 256, 0, s_b>>>(thr, HB);
    cudaEventRecord(ev_b, s_b);

    // ---- half A chain on main ----
    scores_gemm_kernel<<<gs, 256>>>(0);
    select16_kernel<<<HB * SEQ, 256>>>(0);
    cudaStreamWaitEvent(0, ev_v, 0);
    av_gemm_kernel<<<gav, 256>>>(thr, 0);

    // join half B, then output projection
    cudaStreamWaitEvent(0, ev_b, 0);
    dim3 go(HIDDEN / 128, MROWS / 128);
    out_gemm_kernel<<<go, 256>>>(Wo, bo, out);
}

// round 11
// speedup vs baseline: 1.8762x; 1.4036x over previous
#include <cuda_runtime.h>
#include <cuda_bf16.h>
#include <math.h>

#define HIDDEN   1024
#define HEADS    16
#define HEAD_DIM 64
#define BATCH    2
#define SEQ      2048
#define MROWS    (BATCH*SEQ)     // 4096
#define BH       (BATCH*HEADS)   // 32
#define KKEEP    1024

// ---------------------------------------------------------------------------
// Scratch (device globals; no runtime allocation allowed)
// ---------------------------------------------------------------------------
__device__ float    g_Q[(size_t)BH*SEQ*HEAD_DIM];
__device__ float    g_K[(size_t)BH*SEQ*HEAD_DIM];
__device__ float    g_V[(size_t)BH*SEQ*HEAD_DIM];
__device__ float    g_O[(size_t)MROWS*HIDDEN];
__device__ float    g_S[(size_t)BH*SEQ*SEQ];            // fp32 scores, 512MB
__device__ unsigned g_key16[(size_t)BH*SEQ*SEQ/2];      // u16 orderable keys
__device__ float4   g_par[(size_t)BH*SEQ];              // (kthbits, m~, 0, 0)

// ---------------------------------------------------------------------------
// MMA plumbing
// ---------------------------------------------------------------------------
__device__ __forceinline__ unsigned f2tf32(float f) {
    unsigned u;
    asm("cvt.rna.tf32.f32 %0, %1;" : "=r"(u) : "f"(f));
    return u;
}
__device__ __forceinline__ void mma8(float d[4], const uint4& a, const uint2& b) {
    asm("mma.sync.aligned.m16n8k8.row.col.f32.tf32.tf32.f32 "
        "{%0,%1,%2,%3},{%4,%5,%6,%7},{%8,%9},{%0,%1,%2,%3};"
        : "+f"(d[0]), "+f"(d[1]), "+f"(d[2]), "+f"(d[3])
        : "r"(a.x), "r"(a.y), "r"(a.z), "r"(a.w), "r"(b.x), "r"(b.y));
}
__device__ __forceinline__ void mma16(float d[4], const uint4& a, const uint2& b) {
    asm("mma.sync.aligned.m16n8k16.row.col.f32.bf16.bf16.f32 "
        "{%0,%1,%2,%3},{%4,%5,%6,%7},{%8,%9},{%0,%1,%2,%3};"
        : "+f"(d[0]), "+f"(d[1]), "+f"(d[2]), "+f"(d[3])
        : "r"(a.x), "r"(a.y), "r"(a.z), "r"(a.w), "r"(b.x), "r"(b.y));
}

// tf32 frag indexers (k8 granularity, 2 k8 per chunk16)
__device__ __forceinline__ int AIDX(int mt, int k8, int r8, int cx) {
    return ((((mt << 1) + k8) << 3) + r8) * 4 + cx;
}
__device__ __forceinline__ int BIDX(int nt, int k8, int n8, int c) {
    return ((((nt << 1) + k8) << 3) + n8) * 4 + c;
}
// bf16 frag indexers (k16 granularity)
__device__ __forceinline__ int AIDXb(int mt, int r8, int cx) {
    return ((mt << 3) + r8) * 4 + cx;
}
__device__ __forceinline__ int BIDXb(int nt, int n8, int c) {
    return ((nt << 3) + n8) * 4 + c;
}

__device__ __forceinline__ void ldrow(const float* __restrict__ p, float e[8]) {
    float4 a = *(const float4*)p;
    float4 b = *(const float4*)(p + 4);
    e[0]=a.x; e[1]=a.y; e[2]=a.z; e[3]=a.w;
    e[4]=b.x; e[5]=b.y; e[6]=b.z; e[7]=b.w;
}

__device__ __forceinline__ void bsplit(float e, unsigned short& h, unsigned short& l) {
    __nv_bfloat16 bh = __float2bfloat16(e);
    h = __bfloat16_as_ushort(bh);
    l = __bfloat16_as_ushort(__float2bfloat16(e - __bfloat162float(bh)));
}

// ---- bf16 packs (hi + lo) ----
__device__ __forceinline__ void packA16(const float e[8], uint4* Ah, uint4* Al, int tid)
{
    const int lr = tid >> 1, kh = tid & 1;
    const int mt = lr >> 4, rr = lr & 15, r8 = rr & 7, rh = rr >> 3;
    const int comp = rh + (kh << 1);
    #pragma unroll
    for (int c = 0; c < 4; ++c) {
        unsigned short h0, l0, h1, l1;
        bsplit(e[2*c],   h0, l0);
        bsplit(e[2*c+1], h1, l1);
        const int idx = AIDXb(mt, r8, c ^ (r8 & 3));
        ((unsigned*)&Ah[idx])[comp] = (unsigned)h0 | ((unsigned)h1 << 16);
        ((unsigned*)&Al[idx])[comp] = (unsigned)l0 | ((unsigned)l1 << 16);
    }
}
__device__ __forceinline__ void packB16(const float e[8], uint2* Bh, uint2* Bl, int tid)
{
    const int ln = tid >> 1, kh = tid & 1;
    const int nt = ln >> 3, n8 = ln & 7;
    #pragma unroll
    for (int c = 0; c < 4; ++c) {
        unsigned short h0, l0, h1, l1;
        bsplit(e[2*c],   h0, l0);
        bsplit(e[2*c+1], h1, l1);
        const int idx = BIDXb(nt, n8, c);
        ((unsigned*)&Bh[idx])[kh] = (unsigned)h0 | ((unsigned)h1 << 16);
        ((unsigned*)&Bl[idx])[kh] = (unsigned)l0 | ((unsigned)l1 << 16);
    }
}

// ---- tf32 packs ----
__device__ __forceinline__ void packA32(const float e[8], uint4* Ah, int tid)
{
    const int lr = tid >> 1;
    const int mt = lr >> 4, rr = lr & 15, r8 = rr & 7, rh = rr >> 3, k8 = tid & 1;
    #pragma unroll
    for (int j = 0; j < 8; ++j) {
        const int c = j & 3, ch = (j >> 2) & 1;
        const int comp = rh + (ch << 1);
        ((unsigned*)&Ah[AIDX(mt, k8, r8, c ^ (r8 & 3))])[comp] = f2tf32(e[j]);
    }
}
__device__ __forceinline__ unsigned f2u(float f) {
    unsigned b = __float_as_uint(f);
    return (b & 0x80000000u) ? ~b : (b | 0x80000000u);
}
__device__ __forceinline__ float u2f(unsigned u) {
    unsigned b = (u & 0x80000000u) ? (u & 0x7FFFFFFFu) : ~u;
    return __uint_as_float(b);
}
// gate is a plain fp32 threshold: keep iff s >= gate
__device__ __forceinline__ void packA_av(const float e[8], uint4* Ah, int tid,
                                         float gate, float m, float& psum)
{
    const int lr = tid >> 1;
    const int mt = lr >> 4, rr = lr & 15, r8 = rr & 7, rh = rr >> 3, k8 = tid & 1;
    #pragma unroll
    for (int j = 0; j < 8; ++j) {
        const float pe = (e[j] >= gate) ? __expf(e[j] - m) : 0.f;
        psum += pe;
        const int c = j & 3, ch = (j >> 2) & 1;
        const int comp = rh + (ch << 1);
        ((unsigned*)&Ah[AIDX(mt, k8, r8, c ^ (r8 & 3))])[comp] = f2tf32(pe);
    }
}
__device__ __forceinline__ void packB32_nt(const float e[8], uint2* Bh, int tid)
{
    const int ln = tid >> 1;
    const int nt = ln >> 3, n8 = ln & 7, k8 = tid & 1;
    #pragma unroll
    for (int j = 0; j < 8; ++j) {
        const int c = j & 3, ph = (j >> 2) & 1;
        ((unsigned*)&Bh[BIDX(nt, k8, n8, c)])[ph] = f2tf32(e[j]);
    }
}
__device__ __forceinline__ void packB32_nn(const float e[4], uint2* Bh, int tid)
{
    const int kr = tid >> 4, nc = (tid & 15) << 2;
    const int k8 = kr >> 3, c = kr & 3, ph = (kr >> 2) & 1;
    #pragma unroll
    for (int j = 0; j < 4; ++j) {
        const int n = nc + j;
        ((unsigned*)&Bh[BIDX(n >> 3, k8, n & 7, c)])[ph] = f2tf32(e[j]);
    }
}

// ---------------------------------------------------------------------------
// QKV projections (bf16x3, pipelined) -> Q/K/V in [bh, s, d]
// ---------------------------------------------------------------------------
__global__ void __launch_bounds__(256, 2)
qkv_gemm_kernel(const float* __restrict__ x,
                const float* __restrict__ Wq,
                const float* __restrict__ Wk,
                const float* __restrict__ Wv,
                int zbase)
{
    __shared__ uint4 Ah[2][256], Al[2][256];
    __shared__ uint2 Bh[2][512], Bl[2][512];

    const int z = blockIdx.z + zbase;
    const float* W = (z == 0) ? Wq : (z == 1 ? Wk : Wv);
    float*       C = (z == 0) ? g_Q : (z == 1 ? g_K : g_V);

    const int tid = threadIdx.x, lane = tid & 31, wid = tid >> 5;
    const int wm = wid >> 1, wn = wid & 1;
    const int row0 = blockIdx.y * 128, col0 = blockIdx.x * 128;
    const int r8 = lane >> 2, cc = lane & 3, cx = cc ^ (r8 & 3);
    const int lr = tid >> 1, lk = (tid & 1) << 3;

    const float* Ab = x + (size_t)(row0 + lr) * HIDDEN + lk;
    const float* Bb = W + (size_t)(col0 + lr) * HIDDEN + lk;

    float ea[8], eb[8];
    ldrow(Ab, ea); ldrow(Bb, eb);
    packA16(ea, Ah[0], Al[0], tid);
    packB16(eb, Bh[0], Bl[0], tid);
    __syncthreads();

    float d[2][8][4] = {};
    for (int k0 = 0; k0 < HIDDEN; k0 += 16) {
        const int cur = (k0 >> 4) & 1, nxt = cur ^ 1;
        const bool more = (k0 + 16) < HIDDEN;
        if (more) { ldrow(Ab + k0 + 16, ea); ldrow(Bb + k0 + 16, eb); }

        uint4 ah[2], al[2];
        #pragma unroll
        for (int mt = 0; mt < 2; ++mt) {
            ah[mt] = Ah[cur][AIDXb(wm * 2 + mt, r8, cx)];
            al[mt] = Al[cur][AIDXb(wm * 2 + mt, r8, cx)];
        }
        #pragma unroll
        for (int nt = 0; nt < 8; ++nt) {
            const int bi = BIDXb(wn * 8 + nt, r8, cc);
            const uint2 bhv = Bh[cur][bi], blv = Bl[cur][bi];
            #pragma unroll
            for (int mt = 0; mt < 2; ++mt) {
                mma16(d[mt][nt], ah[mt], bhv);
                mma16(d[mt][nt], ah[mt], blv);
                mma16(d[mt][nt], al[mt], bhv);
            }
        }
        if (more) {
            packA16(ea, Ah[nxt], Al[nxt], tid);
            packB16(eb, Bh[nxt], Bl[nxt], tid);
        }
        __syncthreads();
    }

    const int g = lane >> 2, t2 = (lane & 3) << 1;
    #pragma unroll
    for (int mt = 0; mt < 2; ++mt) {
        const int rA = row0 + (wm * 2 + mt) * 16 + g;
        const int rB = rA + 8;
        const int bA = rA >> 11, sA = rA & (SEQ - 1);
        const int bB = rB >> 11, sB = rB & (SEQ - 1);
        #pragma unroll
        for (int nt = 0; nt < 8; ++nt) {
            const int col = col0 + (wn * 8 + nt) * 8 + t2;
            const int h = col >> 6, dd = col & 63;
            *(float2*)&C[(((size_t)(bA * HEADS + h) * SEQ) + sA) * HEAD_DIM + dd] =
                make_float2(d[mt][nt][0], d[mt][nt][1]);
            *(float2*)&C[(((size_t)(bB * HEADS + h) * SEQ) + sB) * HEAD_DIM + dd] =
                make_float2(d[mt][nt][2], d[mt][nt][3]);
        }
    }
}

// ---------------------------------------------------------------------------
// Scores (bf16x3, pipelined): writes fp32 S and u16 orderable keys
// bh = blockIdx.z + bh_base (for split-stream pipelining)
// ---------------------------------------------------------------------------
__global__ void __launch_bounds__(256, 2)
scores_gemm_kernel(int bh_base)
{
    __shared__ uint4 Ah[2][256], Al[2][256];
    __shared__ uint2 Bh[2][512], Bl[2][512];

    const int bh = blockIdx.z + bh_base;
    const float* Qb = g_Q + (size_t)bh * SEQ * HEAD_DIM;
    const float* Kb = g_K + (size_t)bh * SEQ * HEAD_DIM;
    float*       Sb = g_S + (size_t)bh * SEQ * SEQ;
    unsigned*    Kw = g_key16 + (size_t)bh * SEQ * (SEQ / 2);

    const int tid = threadIdx.x, lane = tid & 31, wid = tid >> 5;
    const int wm = wid >> 1, wn = wid & 1;
    const int row0 = blockIdx.y * 128, col0 = blockIdx.x * 128;
    const int r8 = lane >> 2, cc = lane & 3, cx = cc ^ (r8 & 3);
    const int lr = tid >> 1, lk = (tid & 1) << 3;

    const float* Ab = Qb + (size_t)(row0 + lr) * HEAD_DIM + lk;
    const float* Bb = Kb + (size_t)(col0 + lr) * HEAD_DIM + lk;

    float ea[8], eb[8];
    ldrow(Ab, ea); ldrow(Bb, eb);
    packA16(ea, Ah[0], Al[0], tid);
    packB16(eb, Bh[0], Bl[0], tid);
    __syncthreads();

    float d[2][8][4] = {};
    #pragma unroll
    for (int k0 = 0; k0 < HEAD_DIM; k0 += 16) {
        const int cur = (k0 >> 4) & 1, nxt = cur ^ 1;
        const bool more = (k0 + 16) < HEAD_DIM;
        if (more) { ldrow(Ab + k0 + 16, ea); ldrow(Bb + k0 + 16, eb); }

        uint4 ah[2], al[2];
        #pragma unroll
        for (int mt = 0; mt < 2; ++mt) {
            ah[mt] = Ah[cur][AIDXb(wm * 2 + mt, r8, cx)];
            al[mt] = Al[cur][AIDXb(wm * 2 + mt, r8, cx)];
        }
        #pragma unroll
        for (int nt = 0; nt < 8; ++nt) {
            const int bi = BIDXb(wn * 8 + nt, r8, cc);
            const uint2 bhv = Bh[cur][bi], blv = Bl[cur][bi];
            #pragma unroll
            for (int mt = 0; mt < 2; ++mt) {
                mma16(d[mt][nt], ah[mt], bhv);
                mma16(d[mt][nt], ah[mt], blv);
                mma16(d[mt][nt], al[mt], bhv);
            }
        }
        if (more) {
            packA16(ea, Ah[nxt], Al[nxt], tid);
            packB16(eb, Bh[nxt], Bl[nxt], tid);
        }
        __syncthreads();
    }

    const int g = lane >> 2, t2 = (lane & 3) << 1;
    #pragma unroll
    for (int mt = 0; mt < 2; ++mt) {
        const int qA = row0 + (wm * 2 + mt) * 16 + g;
        const int qB = qA + 8;
        #pragma unroll
        for (int nt = 0; nt < 8; ++nt) {
            const int col = col0 + (wn * 8 + nt) * 8 + t2;
            const float a0 = d[mt][nt][0] * 0.125f, a1 = d[mt][nt][1] * 0.125f;
            const float b0 = d[mt][nt][2] * 0.125f, b1 = d[mt][nt][3] * 0.125f;
            *(float2*)&Sb[(size_t)qA * SEQ + col] = make_float2(a0, a1);
            *(float2*)&Sb[(size_t)qB * SEQ + col] = make_float2(b0, b1);
            Kw[((size_t)qA * SEQ + col) >> 1] = (f2u(a0) >> 16) | ((f2u(a1) >> 16) << 16);
            Kw[((size_t)qB * SEQ + col) >> 1] = (f2u(b0) >> 16) | ((f2u(b1) >> 16) << 16);
        }
    }
}

// ---------------------------------------------------------------------------
// select16: per-row max+count; exact radix only when kth >= thr (rare).
//   kth >= thr  <=>  #{key16 >= thr16} >= KKEEP, thr16 = ceil(f2u(thr)/2^16)
// Fast path stores orderable(-inf) so av's gate = max(-inf, thr) = thr.
// ---------------------------------------------------------------------------
__global__ void select16_kernel(const float* __restrict__ thr_ptr, int row_base)
{
    const int tid = threadIdx.x;
    const int row = blockIdx.x + row_base;
    const unsigned* Krow = g_key16 + (size_t)row * (SEQ / 2);

    __shared__ unsigned hist[256];
    __shared__ unsigned wsum[8];
    __shared__ unsigned wcnt[8];
    __shared__ unsigned s_b;
    __shared__ int      s_kk;
    __shared__ unsigned s_max;
    __shared__ unsigned s_cnt;

    uint4 kv = ((const uint4*)Krow)[tid];   // 8 u16 keys
    unsigned k[8] = { kv.x & 0xFFFFu, kv.x >> 16, kv.y & 0xFFFFu, kv.y >> 16,
                      kv.z & 0xFFFFu, kv.z >> 16, kv.w & 0xFFFFu, kv.w >> 16 };

    const int lane = tid & 31, wrp = tid >> 5;

    const float thr = fminf(fmaxf(*thr_ptr, 0.f), 1.f);
    const unsigned thr16 = (f2u(thr) + 0xFFFFu) >> 16;

    // ---- fused row max + count(key >= thr16) ----
    unsigned mk = 0, cnt = 0;
    #pragma unroll
    for (int t = 0; t < 8; ++t) {
        mk = max(mk, k[t]);
        cnt += (k[t] >= thr16) ? 1u : 0u;
    }
    #pragma unroll
    for (int o = 16; o > 0; o >>= 1) {
        mk  = max(mk, __shfl_xor_sync(0xFFFFFFFFu, mk, o));
        cnt += __shfl_xor_sync(0xFFFFFFFFu, cnt, o);
    }
    if (lane == 0) { wsum[wrp] = mk; wcnt[wrp] = cnt; }
    __syncthreads();
    if (tid == 0) {
        unsigned m0 = wsum[0], c0 = wcnt[0];
        #pragma unroll
        for (int w = 1; w < 8; ++w) { m0 = max(m0, wsum[w]); c0 += wcnt[w]; }
        s_max = m0;
        s_cnt = c0;
    }
    __syncthreads();
    const unsigned maxk = s_max;

    // ---- fast path: kth < thr -> gate = thr; exact kth not needed ----
    if (s_cnt < (unsigned)KKEEP) {
        if (tid == 0)
            g_par[row] = make_float4(__uint_as_float(0x007FFFFFu),  // orderable(-inf)
                                     u2f(maxk << 16), 0.f, 0.f);
        return;
    }

    // ---- slow path (rare): exact 2-pass radix for kth ----
    int kk = KKEEP;
    unsigned b1;
    hist[tid] = 0;
    __syncthreads();
    #pragma unroll
    for (int t = 0; t < 8; ++t) {
        const unsigned bin = k[t] >> 8;
        const unsigned peers = __match_any_sync(0xFFFFFFFFu, bin);
        if (lane == (__ffs(peers) - 1))
            atomicAdd(&hist[bin], (unsigned)__popc(peers));
    }
    __syncthreads();
    {
        unsigned myc = hist[tid];
        unsigned cum = myc;
        #pragma unroll
        for (int o = 1; o < 32; o <<= 1) {
            unsigned g2 = __shfl_down_sync(0xFFFFFFFFu, cum, o);
            if (lane + o < 32) cum += g2;
        }
        if (lane == 0) wsum[wrp] = cum;
        __syncthreads();
        unsigned above = 0;
        #pragma unroll
        for (int w = 0; w < 8; ++w) if (w > wrp) above += wsum[w];
        cum += above;
        if (cum >= (unsigned)kk && (cum - myc) < (unsigned)kk) {
            s_b  = (unsigned)tid;
            s_kk = kk - (int)(cum - myc);
        }
    }
    __syncthreads();
    b1 = s_b;
    kk = s_kk;
    __syncthreads();

    hist[tid] = 0;
    __syncthreads();
    #pragma unroll
    for (int t = 0; t < 8; ++t) {
        const bool ok = (k[t] >> 8) == b1;
        const unsigned mok = __ballot_sync(0xFFFFFFFFu, ok);
        if (mok) {
            const unsigned bin = k[t] & 0xFFu;
            const unsigned key = ok ? bin : (256u + (unsigned)lane);
            const unsigned peers = __match_any_sync(0xFFFFFFFFu, key);
            if (ok && lane == (__ffs(peers) - 1))
                atomicAdd(&hist[bin], (unsigned)__popc(peers));
        }
    }
    __syncthreads();
    {
        unsigned myc = hist[tid];
        unsigned cum = myc;
        #pragma unroll
        for (int o = 1; o < 32; o <<= 1) {
            unsigned g2 = __shfl_down_sync(0xFFFFFFFFu, cum, o);
            if (lane + o < 32) cum += g2;
        }
        if (lane == 0) wsum[wrp] = cum;
        __syncthreads();
        unsigned above = 0;
        #pragma unroll
        for (int w = 0; w < 8; ++w) if (w > wrp) above += wsum[w];
        cum += above;
        if (cum >= (unsigned)kk && (cum - myc) < (unsigned)kk)
            s_b = (b1 << 8) | (unsigned)tid;
    }
    __syncthreads();

    if (tid == 0) {
        const unsigned kth16 = s_b;
        g_par[row] = make_float4(__uint_as_float(kth16 << 16),
                                 u2f(maxk << 16), 0.f, 0.f);
    }
}

// ---------------------------------------------------------------------------
// AV (tf32 x1, fused gate+softmax+sum, pipelined) — 256 thr
// bh = blockIdx.y + bh_base
// ---------------------------------------------------------------------------
__global__ void __launch_bounds__(256, 2)
av_gemm_kernel(const float* __restrict__ thr_ptr, int bh_base)
{
    __shared__ uint4 Ah[2][512];
    __shared__ uint2 Bh[2][512];
    __shared__ float rowsum[128];

    const int bh   = blockIdx.y + bh_base;
    const int row0 = blockIdx.x * 128;
    const float* Sb = g_S + (size_t)bh * SEQ * SEQ;
    const float* Vb = g_V + (size_t)bh * SEQ * HEAD_DIM;

    const int tid = threadIdx.x, lane = tid & 31, wid = tid >> 5;
    const int wm = wid >> 1, wn = wid & 1;
    const int r8 = lane >> 2, cc = lane & 3, cx = cc ^ (r8 & 3);
    const int lr = tid >> 1, lk = (tid & 1) << 3;
    const int kr = tid >> 4, nc = (tid & 15) << 2;

    const float4 par = g_par[(size_t)bh * SEQ + row0 + lr];
    const float thr  = fminf(fmaxf(*thr_ptr, 0.f), 1.f);
    const float gate = fmaxf(u2f(__float_as_uint(par.x)), thr);
    const float mrow = par.y;

    const float* Ab = Sb + (size_t)(row0 + lr) * SEQ + lk;
    const float* Bb = Vb + (size_t)kr * HEAD_DIM + nc;

    float psum = 0.f;
    float ea[8], evb[4];
    ldrow(Ab, ea);
    { float4 v = *(const float4*)Bb; evb[0]=v.x; evb[1]=v.y; evb[2]=v.z; evb[3]=v.w; }
    packA_av(ea, Ah[0], tid, gate, mrow, psum);
    packB32_nn(evb, Bh[0], tid);
    __syncthreads();

    float d[2][4][4] = {};
    for (int k0 = 0; k0 < SEQ; k0 += 16) {
        const int cur = (k0 >> 4) & 1, nxt = cur ^ 1;
        const bool more = (k0 + 16) < SEQ;
        if (more) {
            ldrow(Ab + k0 + 16, ea);
            float4 v = *(const float4*)(Bb + (size_t)(k0 + 16) * HEAD_DIM);
            evb[0]=v.x; evb[1]=v.y; evb[2]=v.z; evb[3]=v.w;
        }

        #pragma unroll
        for (int k8 = 0; k8 < 2; ++k8) {
            uint4 ah[2];
            #pragma unroll
            for (int mt = 0; mt < 2; ++mt)
                ah[mt] = Ah[cur][AIDX(wm * 2 + mt, k8, r8, cx)];
            #pragma unroll
            for (int nt = 0; nt < 4; ++nt) {
                const uint2 bv = Bh[cur][BIDX(wn * 4 + nt, k8, r8, cc)];
                #pragma unroll
                for (int mt = 0; mt < 2; ++mt)
                    mma8(d[mt][nt], ah[mt], bv);
            }
        }
        if (more) {
            packA_av(ea, Ah[nxt], tid, gate, mrow, psum);
            packB32_nn(evb, Bh[nxt], tid);
        }
        __syncthreads();
    }

    {
        const float tot = psum + __shfl_xor_sync(0xFFFFFFFFu, psum, 1);
        if ((tid & 1) == 0) rowsum[lr] = tot;
    }
    __syncthreads();

    const int b = bh >> 4, h = bh & 15;
    const int g = lane >> 2, t2 = (lane & 3) << 1;
    #pragma unroll
    for (int mt = 0; mt < 2; ++mt) {
        const int qA = row0 + (wm * 2 + mt) * 16 + g;
        const int qB = qA + 8;
        const float invA = 1.f / rowsum[qA - row0];
        const float invB = 1.f / rowsum[qB - row0];
        #pragma unroll
        for (int nt = 0; nt < 4; ++nt) {
            const int col = (wn * 4 + nt) * 8 + t2;
            *(float2*)&g_O[(((size_t)b * SEQ + qA) * HIDDEN) + h * HEAD_DIM + col] =
                make_float2(d[mt][nt][0] * invA, d[mt][nt][1] * invA);
            *(float2*)&g_O[(((size_t)b * SEQ + qB) * HIDDEN) + h * HEAD_DIM + col] =
                make_float2(d[mt][nt][2] * invB, d[mt][nt][3] * invB);
        }
    }
}

// ---------------------------------------------------------------------------
// Output projection (tf32 x1, pipelined): Y = g_O @ Wo^T + bo
// ---------------------------------------------------------------------------
__global__ void __launch_bounds__(256, 2)
out_gemm_kernel(const float* __restrict__ Wo,
                const float* __restrict__ bo,
                float* __restrict__ Y)
{
    __shared__ uint4 Ah[2][512];
    __shared__ uint2 Bh[2][1024];

    const int tid = threadIdx.x, lane = tid & 31, wid = tid >> 5;
    const int wm = wid >> 1, wn = wid & 1;
    const int row0 = blockIdx.y * 128, col0 = blockIdx.x * 128;
    const int r8 = lane >> 2, cc = lane & 3, cx = cc ^ (r8 & 3);
    const int lr = tid >> 1, lk = (tid & 1) << 3;

    const float* Ab = g_O + (size_t)(row0 + lr) * HIDDEN + lk;
    const float* Bb = Wo  + (size_t)(col0 + lr) * HIDDEN + lk;

    float ea[8], eb[8];
    ldrow(Ab, ea); ldrow(Bb, eb);
    packA32(ea, Ah[0], tid);
    packB32_nt(eb, Bh[0], tid);
    __syncthreads();

    float d[2][8][4] = {};
    for (int k0 = 0; k0 < HIDDEN; k0 += 16) {
        const int cur = (k0 >> 4) & 1, nxt = cur ^ 1;
        const bool more = (k0 + 16) < HIDDEN;
        if (more) { ldrow(Ab + k0 + 16, ea); ldrow(Bb + k0 + 16, eb); }

        #pragma unroll
        for (int k8 = 0; k8 < 2; ++k8) {
            uint4 ah[2];
            #pragma unroll
            for (int mt = 0; mt < 2; ++mt)
                ah[mt] = Ah[cur][AIDX(wm * 2 + mt, k8, r8, cx)];
            #pragma unroll
            for (int nt = 0; nt < 8; ++nt) {
                const uint2 bv = Bh[cur][BIDX(wn * 8 + nt, k8, r8, cc)];
                #pragma unroll
                for (int mt = 0; mt < 2; ++mt)
                    mma8(d[mt][nt], ah[mt], bv);
            }
        }
        if (more) {
            packA32(ea, Ah[nxt], tid);
            packB32_nt(eb, Bh[nxt], tid);
        }
        __syncthreads();
    }

    const int g = lane >> 2, t2 = (lane & 3) << 1;
    #pragma unroll
    for (int mt = 0; mt < 2; ++mt) {
        const int rA = row0 + (wm * 2 + mt) * 16 + g;
        const int rB = rA + 8;
        #pragma unroll
        for (int nt = 0; nt < 8; ++nt) {
            const int col = col0 + (wn * 8 + nt) * 8 + t2;
            const float b0 = bo[col], b1 = bo[col + 1];
            *(float2*)&Y[(size_t)rA * HIDDEN + col] =
                make_float2(d[mt][nt][0] + b0, d[mt][nt][1] + b1);
            *(float2*)&Y[(size_t)rB * HIDDEN + col] =
                make_float2(d[mt][nt][2] + b0, d[mt][nt][3] + b1);
        }
    }
}

// ---------------------------------------------------------------------------
// Launch: V projection on side stream s_v; scores->select->av split into two
// bh-halves, half B pipelined on stream s_b. Resources created once, outside
// capture (first call is the uncaptured correctness run).
// ---------------------------------------------------------------------------
extern "C" void kernel_launch(void* const* d_in, const int* in_sizes, int n_in,
                              void* d_out, int out_size)
{
    const float* x   = (const float*)d_in[0];
    const float* Wq  = (const float*)d_in[1];
    const float* Wk  = (const float*)d_in[2];
    const float* Wv  = (const float*)d_in[3];
    const float* Wo  = (const float*)d_in[4];
    const float* bo  = (const float*)d_in[5];
    const float* thr = (const float*)d_in[6];
    float* out = (float*)d_out;

    static cudaStream_t s_v = nullptr, s_b = nullptr;
    static cudaEvent_t  ev_fork = nullptr, ev_v = nullptr,
                        ev_qk = nullptr, ev_b = nullptr;
    if (s_v == nullptr) {
        cudaStreamCreateWithFlags(&s_v, cudaStreamNonBlocking);
        cudaStreamCreateWithFlags(&s_b, cudaStreamNonBlocking);
        cudaEventCreateWithFlags(&ev_fork, cudaEventDisableTiming);
        cudaEventCreateWithFlags(&ev_v,    cudaEventDisableTiming);
        cudaEventCreateWithFlags(&ev_qk,   cudaEventDisableTiming);
        cudaEventCreateWithFlags(&ev_b,    cudaEventDisableTiming);
    }

    const int HB = BH / 2;   // 16 heads per half

    cudaEventRecord(ev_fork, 0);
    cudaStreamWaitEvent(s_v, ev_fork, 0);

    // V projection on s_v
    dim3 gv(HIDDEN / 128, MROWS / 128, 1);
    qkv_gemm_kernel<<<gv, 256, 0, s_v>>>(x, Wq, Wk, Wv, 2);
    cudaEventRecord(ev_v, s_v);

    // Q,K projections on main
    dim3 gqk(HIDDEN / 128, MROWS / 128, 2);
    qkv_gemm_kernel<<<gqk, 256>>>(x, Wq, Wk, Wv, 0);
    cudaEventRecord(ev_qk, 0);

    // ---- half B chain on s_b ----
    cudaStreamWaitEvent(s_b, ev_qk, 0);
    dim3 gs(SEQ / 128, SEQ / 128, HB);
    scores_gemm_kernel<<<gs, 256, 0, s_b>>>(HB);
    select16_kernel<<<HB * SEQ, 256, 0, s_b>>>(thr, HB * SEQ);
    cudaStreamWaitEvent(s_b, ev_v, 0);
    dim3 gav(SEQ / 128, HB);
    av_gemm_kernel<<<gav, 256, 0, s_b>>>(thr, HB);
    cudaEventRecord(ev_b, s_b);

    // ---- half A chain on main ----
    scores_gemm_kernel<<<gs, 256>>>(0);
    select16_kernel<<<HB * SEQ, 256>>>(thr, 0);
    cudaStreamWaitEvent(0, ev_v, 0);
    av_gemm_kernel<<<gav, 256>>>(thr, 0);

    // join half B, then output projection
    cudaStreamWaitEvent(0, ev_b, 0);
    dim3 go(HIDDEN / 128, MROWS / 128);
    out_gemm_kernel<<<go, 256>>>(Wo, bo, out);
}

// round 12
// speedup vs baseline: 2.0519x; 1.0936x over previous
#include <cuda_runtime.h>
#include <cuda_bf16.h>
#include <math.h>

#define HIDDEN   1024
#define HEADS    16
#define HEAD_DIM 64
#define BATCH    2
#define SEQ      2048
#define MROWS    (BATCH*SEQ)     // 4096
#define BH       (BATCH*HEADS)   // 32
#define KKEEP    1024
#define NROWS    (BH*SEQ)        // 65536
#define HROWS    (NROWS/2)       // rows per half

// ---------------------------------------------------------------------------
// Scratch (device globals; no runtime allocation allowed)
// ---------------------------------------------------------------------------
__device__ float    g_Q[(size_t)BH*SEQ*HEAD_DIM];
__device__ float    g_K[(size_t)BH*SEQ*HEAD_DIM];
__device__ float    g_V[(size_t)BH*SEQ*HEAD_DIM];
__device__ float    g_O[(size_t)MROWS*HIDDEN];
__device__ float    g_S[(size_t)BH*SEQ*SEQ];      // fp32 scores, 512MB
__device__ float4   g_par[NROWS];                 // (kthbits, m~, 0, 0)
__device__ unsigned g_cnt[NROWS];                 // per-row count(key>=thr16)
__device__ unsigned g_maxk[NROWS];                // per-row max key16
__device__ unsigned g_nslow[2];                   // slow-row counters (per half)
__device__ unsigned g_slowlist[2][HROWS];         // slow-row lists

// ---------------------------------------------------------------------------
// MMA plumbing
// ---------------------------------------------------------------------------
__device__ __forceinline__ unsigned f2tf32(float f) {
    unsigned u;
    asm("cvt.rna.tf32.f32 %0, %1;" : "=r"(u) : "f"(f));
    return u;
}
__device__ __forceinline__ void mma8(float d[4], const uint4& a, const uint2& b) {
    asm("mma.sync.aligned.m16n8k8.row.col.f32.tf32.tf32.f32 "
        "{%0,%1,%2,%3},{%4,%5,%6,%7},{%8,%9},{%0,%1,%2,%3};"
        : "+f"(d[0]), "+f"(d[1]), "+f"(d[2]), "+f"(d[3])
        : "r"(a.x), "r"(a.y), "r"(a.z), "r"(a.w), "r"(b.x), "r"(b.y));
}
__device__ __forceinline__ void mma16(float d[4], const uint4& a, const uint2& b) {
    asm("mma.sync.aligned.m16n8k16.row.col.f32.bf16.bf16.f32 "
        "{%0,%1,%2,%3},{%4,%5,%6,%7},{%8,%9},{%0,%1,%2,%3};"
        : "+f"(d[0]), "+f"(d[1]), "+f"(d[2]), "+f"(d[3])
        : "r"(a.x), "r"(a.y), "r"(a.z), "r"(a.w), "r"(b.x), "r"(b.y));
}

// tf32 frag indexers (k8 granularity, 2 k8 per chunk16)
__device__ __forceinline__ int AIDX(int mt, int k8, int r8, int cx) {
    return ((((mt << 1) + k8) << 3) + r8) * 4 + cx;
}
__device__ __forceinline__ int BIDX(int nt, int k8, int n8, int c) {
    return ((((nt << 1) + k8) << 3) + n8) * 4 + c;
}
// bf16 frag indexers (k16 granularity)
__device__ __forceinline__ int AIDXb(int mt, int r8, int cx) {
    return ((mt << 3) + r8) * 4 + cx;
}
__device__ __forceinline__ int BIDXb(int nt, int n8, int c) {
    return ((nt << 3) + n8) * 4 + c;
}

__device__ __forceinline__ void ldrow(const float* __restrict__ p, float e[8]) {
    float4 a = *(const float4*)p;
    float4 b = *(const float4*)(p + 4);
    e[0]=a.x; e[1]=a.y; e[2]=a.z; e[3]=a.w;
    e[4]=b.x; e[5]=b.y; e[6]=b.z; e[7]=b.w;
}

__device__ __forceinline__ void bsplit(float e, unsigned short& h, unsigned short& l) {
    __nv_bfloat16 bh = __float2bfloat16(e);
    h = __bfloat16_as_ushort(bh);
    l = __bfloat16_as_ushort(__float2bfloat16(e - __bfloat162float(bh)));
}

// ---- bf16 packs (hi + lo) ----
__device__ __forceinline__ void packA16(const float e[8], uint4* Ah, uint4* Al, int tid)
{
    const int lr = tid >> 1, kh = tid & 1;
    const int mt = lr >> 4, rr = lr & 15, r8 = rr & 7, rh = rr >> 3;
    const int comp = rh + (kh << 1);
    #pragma unroll
    for (int c = 0; c < 4; ++c) {
        unsigned short h0, l0, h1, l1;
        bsplit(e[2*c],   h0, l0);
        bsplit(e[2*c+1], h1, l1);
        const int idx = AIDXb(mt, r8, c ^ (r8 & 3));
        ((unsigned*)&Ah[idx])[comp] = (unsigned)h0 | ((unsigned)h1 << 16);
        ((unsigned*)&Al[idx])[comp] = (unsigned)l0 | ((unsigned)l1 << 16);
    }
}
__device__ __forceinline__ void packB16(const float e[8], uint2* Bh, uint2* Bl, int tid)
{
    const int ln = tid >> 1, kh = tid & 1;
    const int nt = ln >> 3, n8 = ln & 7;
    #pragma unroll
    for (int c = 0; c < 4; ++c) {
        unsigned short h0, l0, h1, l1;
        bsplit(e[2*c],   h0, l0);
        bsplit(e[2*c+1], h1, l1);
        const int idx = BIDXb(nt, n8, c);
        ((unsigned*)&Bh[idx])[kh] = (unsigned)h0 | ((unsigned)h1 << 16);
        ((unsigned*)&Bl[idx])[kh] = (unsigned)l0 | ((unsigned)l1 << 16);
    }
}

// ---- tf32 packs ----
__device__ __forceinline__ void packA32(const float e[8], uint4* Ah, int tid)
{
    const int lr = tid >> 1;
    const int mt = lr >> 4, rr = lr & 15, r8 = rr & 7, rh = rr >> 3, k8 = tid & 1;
    #pragma unroll
    for (int j = 0; j < 8; ++j) {
        const int c = j & 3, ch = (j >> 2) & 1;
        const int comp = rh + (ch << 1);
        ((unsigned*)&Ah[AIDX(mt, k8, r8, c ^ (r8 & 3))])[comp] = f2tf32(e[j]);
    }
}
__device__ __forceinline__ unsigned f2u(float f) {
    unsigned b = __float_as_uint(f);
    return (b & 0x80000000u) ? ~b : (b | 0x80000000u);
}
__device__ __forceinline__ float u2f(unsigned u) {
    unsigned b = (u & 0x80000000u) ? (u & 0x7FFFFFFFu) : ~u;
    return __uint_as_float(b);
}
// gate is a plain fp32 threshold: keep iff s >= gate
__device__ __forceinline__ void packA_av(const float e[8], uint4* Ah, int tid,
                                         float gate, float m, float& psum)
{
    const int lr = tid >> 1;
    const int mt = lr >> 4, rr = lr & 15, r8 = rr & 7, rh = rr >> 3, k8 = tid & 1;
    #pragma unroll
    for (int j = 0; j < 8; ++j) {
        const float pe = (e[j] >= gate) ? __expf(e[j] - m) : 0.f;
        psum += pe;
        const int c = j & 3, ch = (j >> 2) & 1;
        const int comp = rh + (ch << 1);
        ((unsigned*)&Ah[AIDX(mt, k8, r8, c ^ (r8 & 3))])[comp] = f2tf32(pe);
    }
}
__device__ __forceinline__ void packB32_nt(const float e[8], uint2* Bh, int tid)
{
    const int ln = tid >> 1;
    const int nt = ln >> 3, n8 = ln & 7, k8 = tid & 1;
    #pragma unroll
    for (int j = 0; j < 8; ++j) {
        const int c = j & 3, ph = (j >> 2) & 1;
        ((unsigned*)&Bh[BIDX(nt, k8, n8, c)])[ph] = f2tf32(e[j]);
    }
}
__device__ __forceinline__ void packB32_nn(const float e[4], uint2* Bh, int tid)
{
    const int kr = tid >> 4, nc = (tid & 15) << 2;
    const int k8 = kr >> 3, c = kr & 3, ph = (kr >> 2) & 1;
    #pragma unroll
    for (int j = 0; j < 4; ++j) {
        const int n = nc + j;
        ((unsigned*)&Bh[BIDX(n >> 3, k8, n & 7, c)])[ph] = f2tf32(e[j]);
    }
}

// ---------------------------------------------------------------------------
// QKV projections (bf16x3, pipelined) -> Q/K/V in [bh, s, d]
// ---------------------------------------------------------------------------
__global__ void __launch_bounds__(256, 2)
qkv_gemm_kernel(const float* __restrict__ x,
                const float* __restrict__ Wq,
                const float* __restrict__ Wk,
                const float* __restrict__ Wv,
                int zbase)
{
    __shared__ uint4 Ah[2][256], Al[2][256];
    __shared__ uint2 Bh[2][512], Bl[2][512];

    const int z = blockIdx.z + zbase;
    const float* W = (z == 0) ? Wq : (z == 1 ? Wk : Wv);
    float*       C = (z == 0) ? g_Q : (z == 1 ? g_K : g_V);

    const int tid = threadIdx.x, lane = tid & 31, wid = tid >> 5;
    const int wm = wid >> 1, wn = wid & 1;
    const int row0 = blockIdx.y * 128, col0 = blockIdx.x * 128;
    const int r8 = lane >> 2, cc = lane & 3, cx = cc ^ (r8 & 3);
    const int lr = tid >> 1, lk = (tid & 1) << 3;

    const float* Ab = x + (size_t)(row0 + lr) * HIDDEN + lk;
    const float* Bb = W + (size_t)(col0 + lr) * HIDDEN + lk;

    float ea[8], eb[8];
    ldrow(Ab, ea); ldrow(Bb, eb);
    packA16(ea, Ah[0], Al[0], tid);
    packB16(eb, Bh[0], Bl[0], tid);
    __syncthreads();

    float d[2][8][4] = {};
    for (int k0 = 0; k0 < HIDDEN; k0 += 16) {
        const int cur = (k0 >> 4) & 1, nxt = cur ^ 1;
        const bool more = (k0 + 16) < HIDDEN;
        if (more) { ldrow(Ab + k0 + 16, ea); ldrow(Bb + k0 + 16, eb); }

        uint4 ah[2], al[2];
        #pragma unroll
        for (int mt = 0; mt < 2; ++mt) {
            ah[mt] = Ah[cur][AIDXb(wm * 2 + mt, r8, cx)];
            al[mt] = Al[cur][AIDXb(wm * 2 + mt, r8, cx)];
        }
        #pragma unroll
        for (int nt = 0; nt < 8; ++nt) {
            const int bi = BIDXb(wn * 8 + nt, r8, cc);
            const uint2 bhv = Bh[cur][bi], blv = Bl[cur][bi];
            #pragma unroll
            for (int mt = 0; mt < 2; ++mt) {
                mma16(d[mt][nt], ah[mt], bhv);
                mma16(d[mt][nt], ah[mt], blv);
                mma16(d[mt][nt], al[mt], bhv);
            }
        }
        if (more) {
            packA16(ea, Ah[nxt], Al[nxt], tid);
            packB16(eb, Bh[nxt], Bl[nxt], tid);
        }
        __syncthreads();
    }

    const int g = lane >> 2, t2 = (lane & 3) << 1;
    #pragma unroll
    for (int mt = 0; mt < 2; ++mt) {
        const int rA = row0 + (wm * 2 + mt) * 16 + g;
        const int rB = rA + 8;
        const int bA = rA >> 11, sA = rA & (SEQ - 1);
        const int bB = rB >> 11, sB = rB & (SEQ - 1);
        #pragma unroll
        for (int nt = 0; nt < 8; ++nt) {
            const int col = col0 + (wn * 8 + nt) * 8 + t2;
            const int h = col >> 6, dd = col & 63;
            *(float2*)&C[(((size_t)(bA * HEADS + h) * SEQ) + sA) * HEAD_DIM + dd] =
                make_float2(d[mt][nt][0], d[mt][nt][1]);
            *(float2*)&C[(((size_t)(bB * HEADS + h) * SEQ) + sB) * HEAD_DIM + dd] =
                make_float2(d[mt][nt][2], d[mt][nt][3]);
        }
    }
}

// ---------------------------------------------------------------------------
// Scores (bf16x3, pipelined): writes fp32 S; accumulates per-row
// count(key16 >= thr16) and max(key16) via global atomics (no key array).
// ---------------------------------------------------------------------------
__global__ void __launch_bounds__(256, 2)
scores_gemm_kernel(const float* __restrict__ thr_ptr, int bh_base)
{
    __shared__ uint4 Ah[2][256], Al[2][256];
    __shared__ uint2 Bh[2][512], Bl[2][512];

    const int bh = blockIdx.z + bh_base;
    const float* Qb = g_Q + (size_t)bh * SEQ * HEAD_DIM;
    const float* Kb = g_K + (size_t)bh * SEQ * HEAD_DIM;
    float*       Sb = g_S + (size_t)bh * SEQ * SEQ;

    const int tid = threadIdx.x, lane = tid & 31, wid = tid >> 5;
    const int wm = wid >> 1, wn = wid & 1;
    const int row0 = blockIdx.y * 128, col0 = blockIdx.x * 128;
    const int r8 = lane >> 2, cc = lane & 3, cx = cc ^ (r8 & 3);
    const int lr = tid >> 1, lk = (tid & 1) << 3;

    const float* Ab = Qb + (size_t)(row0 + lr) * HEAD_DIM + lk;
    const float* Bb = Kb + (size_t)(col0 + lr) * HEAD_DIM + lk;

    float ea[8], eb[8];
    ldrow(Ab, ea); ldrow(Bb, eb);
    packA16(ea, Ah[0], Al[0], tid);
    packB16(eb, Bh[0], Bl[0], tid);
    __syncthreads();

    float d[2][8][4] = {};
    #pragma unroll
    for (int k0 = 0; k0 < HEAD_DIM; k0 += 16) {
        const int cur = (k0 >> 4) & 1, nxt = cur ^ 1;
        const bool more = (k0 + 16) < HEAD_DIM;
        if (more) { ldrow(Ab + k0 + 16, ea); ldrow(Bb + k0 + 16, eb); }

        uint4 ah[2], al[2];
        #pragma unroll
        for (int mt = 0; mt < 2; ++mt) {
            ah[mt] = Ah[cur][AIDXb(wm * 2 + mt, r8, cx)];
            al[mt] = Al[cur][AIDXb(wm * 2 + mt, r8, cx)];
        }
        #pragma unroll
        for (int nt = 0; nt < 8; ++nt) {
            const int bi = BIDXb(wn * 8 + nt, r8, cc);
            const uint2 bhv = Bh[cur][bi], blv = Bl[cur][bi];
            #pragma unroll
            for (int mt = 0; mt < 2; ++mt) {
                mma16(d[mt][nt], ah[mt], bhv);
                mma16(d[mt][nt], ah[mt], blv);
                mma16(d[mt][nt], al[mt], bhv);
            }
        }
        if (more) {
            packA16(ea, Ah[nxt], Al[nxt], tid);
            packB16(eb, Bh[nxt], Bl[nxt], tid);
        }
        __syncthreads();
    }

    const float thrv = fminf(fmaxf(*thr_ptr, 0.f), 1.f);
    const unsigned thr16 = (f2u(thrv) + 0xFFFFu) >> 16;

    const int g = lane >> 2, t2 = (lane & 3) << 1;
    #pragma unroll
    for (int mt = 0; mt < 2; ++mt) {
        const int qA = row0 + (wm * 2 + mt) * 16 + g;
        const int qB = qA + 8;
        unsigned cA = 0, cB = 0, mA = 0, mB = 0;
        #pragma unroll
        for (int nt = 0; nt < 8; ++nt) {
            const int col = col0 + (wn * 8 + nt) * 8 + t2;
            const float a0 = d[mt][nt][0] * 0.125f, a1 = d[mt][nt][1] * 0.125f;
            const float b0 = d[mt][nt][2] * 0.125f, b1 = d[mt][nt][3] * 0.125f;
            *(float2*)&Sb[(size_t)qA * SEQ + col] = make_float2(a0, a1);
            *(float2*)&Sb[(size_t)qB * SEQ + col] = make_float2(b0, b1);
            const unsigned kA0 = f2u(a0) >> 16, kA1 = f2u(a1) >> 16;
            const unsigned kB0 = f2u(b0) >> 16, kB1 = f2u(b1) >> 16;
            cA += (kA0 >= thr16) + (kA1 >= thr16);
            cB += (kB0 >= thr16) + (kB1 >= thr16);
            mA = max(mA, max(kA0, kA1));
            mB = max(mB, max(kB0, kB1));
        }
        const size_t rgA = (size_t)bh * SEQ + qA;
        const size_t rgB = (size_t)bh * SEQ + qB;
        atomicAdd(&g_cnt[rgA], cA);
        atomicAdd(&g_cnt[rgB], cB);
        atomicMax(&g_maxk[rgA], mA);
        atomicMax(&g_maxk[rgB], mB);
    }
}

// ---------------------------------------------------------------------------
// select_fast: one thread per row. Fast path (cnt < KKEEP): gate = thr.
// Rare slow rows appended to per-half list.
// ---------------------------------------------------------------------------
__global__ void select_fast_kernel(int row_base, int half)
{
    const int row = row_base + blockIdx.x * blockDim.x + threadIdx.x;
    const unsigned cnt = g_cnt[row];
    const unsigned mk  = g_maxk[row];
    if (cnt < (unsigned)KKEEP) {
        g_par[row] = make_float4(__uint_as_float(0x007FFFFFu),  // orderable(-inf)
                                 u2f(mk << 16), 0.f, 0.f);
    } else {
        const unsigned i = atomicAdd(&g_nslow[half], 1u);
        g_slowlist[half][i] = (unsigned)row;
    }
}

// ---------------------------------------------------------------------------
// select_slow: persistent blocks drain the slow list; exact 2-pass radix on
// key16 recomputed from fp32 S (bit-identical to the round-11 slow path).
// ---------------------------------------------------------------------------
__global__ void select_slow_kernel(int half)
{
    __shared__ unsigned hist[256];
    __shared__ unsigned wsum[8];
    __shared__ unsigned s_b;
    __shared__ int      s_kk;

    const int tid = threadIdx.x;
    const int lane = tid & 31, wrp = tid >> 5;
    const unsigned n = *((volatile unsigned*)&g_nslow[half]);

    for (unsigned it = blockIdx.x; it < n; it += gridDim.x) {
        const int row = (int)g_slowlist[half][it];
        const float* Srow = g_S + (size_t)row * SEQ;

        float4 v0 = ((const float4*)Srow)[tid];
        float4 v1 = ((const float4*)Srow)[256 + tid];
        const float sv[8] = {v0.x, v0.y, v0.z, v0.w, v1.x, v1.y, v1.z, v1.w};
        unsigned k[8];
        #pragma unroll
        for (int t = 0; t < 8; ++t) k[t] = f2u(sv[t]) >> 16;

        // ---- pass 1 (high byte) ----
        int kk = KKEEP;
        unsigned b1;
        hist[tid] = 0;
        __syncthreads();
        #pragma unroll
        for (int t = 0; t < 8; ++t) {
            const unsigned bin = k[t] >> 8;
            const unsigned peers = __match_any_sync(0xFFFFFFFFu, bin);
            if (lane == (__ffs(peers) - 1))
                atomicAdd(&hist[bin], (unsigned)__popc(peers));
        }
        __syncthreads();
        {
            unsigned myc = hist[tid];
            unsigned cum = myc;
            #pragma unroll
            for (int o = 1; o < 32; o <<= 1) {
                unsigned g2 = __shfl_down_sync(0xFFFFFFFFu, cum, o);
                if (lane + o < 32) cum += g2;
            }
            if (lane == 0) wsum[wrp] = cum;
            __syncthreads();
            unsigned above = 0;
            #pragma unroll
            for (int w = 0; w < 8; ++w) if (w > wrp) above += wsum[w];
            cum += above;
            if (cum >= (unsigned)kk && (cum - myc) < (unsigned)kk) {
                s_b  = (unsigned)tid;
                s_kk = kk - (int)(cum - myc);
            }
        }
        __syncthreads();
        b1 = s_b;
        kk = s_kk;
        __syncthreads();

        // ---- pass 2 (low byte, among prefix matches) ----
        hist[tid] = 0;
        __syncthreads();
        #pragma unroll
        for (int t = 0; t < 8; ++t) {
            const bool ok = (k[t] >> 8) == b1;
            const unsigned mok = __ballot_sync(0xFFFFFFFFu, ok);
            if (mok) {
                const unsigned bin = k[t] & 0xFFu;
                const unsigned key = ok ? bin : (256u + (unsigned)lane);
                const unsigned peers = __match_any_sync(0xFFFFFFFFu, key);
                if (ok && lane == (__ffs(peers) - 1))
                    atomicAdd(&hist[bin], (unsigned)__popc(peers));
            }
        }
        __syncthreads();
        {
            unsigned myc = hist[tid];
            unsigned cum = myc;
            #pragma unroll
            for (int o = 1; o < 32; o <<= 1) {
                unsigned g2 = __shfl_down_sync(0xFFFFFFFFu, cum, o);
                if (lane + o < 32) cum += g2;
            }
            if (lane == 0) wsum[wrp] = cum;
            __syncthreads();
            unsigned above = 0;
            #pragma unroll
            for (int w = 0; w < 8; ++w) if (w > wrp) above += wsum[w];
            cum += above;
            if (cum >= (unsigned)kk && (cum - myc) < (unsigned)kk)
                s_b = (b1 << 8) | (unsigned)tid;
        }
        __syncthreads();

        if (tid == 0) {
            const unsigned kth16 = s_b;
            g_par[row] = make_float4(__uint_as_float(kth16 << 16),
                                     u2f(g_maxk[row] << 16), 0.f, 0.f);
        }
        __syncthreads();
    }
}

// ---------------------------------------------------------------------------
// AV (tf32 x1, fused gate+softmax+sum, pipelined) — 256 thr
// ---------------------------------------------------------------------------
__global__ void __launch_bounds__(256, 2)
av_gemm_kernel(const float* __restrict__ thr_ptr, int bh_base)
{
    __shared__ uint4 Ah[2][512];
    __shared__ uint2 Bh[2][512];
    __shared__ float rowsum[128];

    const int bh   = blockIdx.y + bh_base;
    const int row0 = blockIdx.x * 128;
    const float* Sb = g_S + (size_t)bh * SEQ * SEQ;
    const float* Vb = g_V + (size_t)bh * SEQ * HEAD_DIM;

    const int tid = threadIdx.x, lane = tid & 31, wid = tid >> 5;
    const int wm = wid >> 1, wn = wid & 1;
    const int r8 = lane >> 2, cc = lane & 3, cx = cc ^ (r8 & 3);
    const int lr = tid >> 1, lk = (tid & 1) << 3;
    const int kr = tid >> 4, nc = (tid & 15) << 2;

    const float4 par = g_par[(size_t)bh * SEQ + row0 + lr];
    const float thr  = fminf(fmaxf(*thr_ptr, 0.f), 1.f);
    const float gate = fmaxf(u2f(__float_as_uint(par.x)), thr);
    const float mrow = par.y;

    const float* Ab = Sb + (size_t)(row0 + lr) * SEQ + lk;
    const float* Bb = Vb + (size_t)kr * HEAD_DIM + nc;

    float psum = 0.f;
    float ea[8], evb[4];
    ldrow(Ab, ea);
    { float4 v = *(const float4*)Bb; evb[0]=v.x; evb[1]=v.y; evb[2]=v.z; evb[3]=v.w; }
    packA_av(ea, Ah[0], tid, gate, mrow, psum);
    packB32_nn(evb, Bh[0], tid);
    __syncthreads();

    float d[2][4][4] = {};
    for (int k0 = 0; k0 < SEQ; k0 += 16) {
        const int cur = (k0 >> 4) & 1, nxt = cur ^ 1;
        const bool more = (k0 + 16) < SEQ;
        if (more) {
            ldrow(Ab + k0 + 16, ea);
            float4 v = *(const float4*)(Bb + (size_t)(k0 + 16) * HEAD_DIM);
            evb[0]=v.x; evb[1]=v.y; evb[2]=v.z; evb[3]=v.w;
        }

        #pragma unroll
        for (int k8 = 0; k8 < 2; ++k8) {
            uint4 ah[2];
            #pragma unroll
            for (int mt = 0; mt < 2; ++mt)
                ah[mt] = Ah[cur][AIDX(wm * 2 + mt, k8, r8, cx)];
            #pragma unroll
            for (int nt = 0; nt < 4; ++nt) {
                const uint2 bv = Bh[cur][BIDX(wn * 4 + nt, k8, r8, cc)];
                #pragma unroll
                for (int mt = 0; mt < 2; ++mt)
                    mma8(d[mt][nt], ah[mt], bv);
            }
        }
        if (more) {
            packA_av(ea, Ah[nxt], tid, gate, mrow, psum);
            packB32_nn(evb, Bh[nxt], tid);
        }
        __syncthreads();
    }

    {
        const float tot = psum + __shfl_xor_sync(0xFFFFFFFFu, psum, 1);
        if ((tid & 1) == 0) rowsum[lr] = tot;
    }
    __syncthreads();

    const int b = bh >> 4, h = bh & 15;
    const int g = lane >> 2, t2 = (lane & 3) << 1;
    #pragma unroll
    for (int mt = 0; mt < 2; ++mt) {
        const int qA = row0 + (wm * 2 + mt) * 16 + g;
        const int qB = qA + 8;
        const float invA = 1.f / rowsum[qA - row0];
        const float invB = 1.f / rowsum[qB - row0];
        #pragma unroll
        for (int nt = 0; nt < 4; ++nt) {
            const int col = (wn * 4 + nt) * 8 + t2;
            *(float2*)&g_O[(((size_t)b * SEQ + qA) * HIDDEN) + h * HEAD_DIM + col] =
                make_float2(d[mt][nt][0] * invA, d[mt][nt][1] * invA);
            *(float2*)&g_O[(((size_t)b * SEQ + qB) * HIDDEN) + h * HEAD_DIM + col] =
                make_float2(d[mt][nt][2] * invB, d[mt][nt][3] * invB);
        }
    }
}

// ---------------------------------------------------------------------------
// Output projection (tf32 x1, pipelined): Y = g_O @ Wo^T + bo
// ---------------------------------------------------------------------------
__global__ void __launch_bounds__(256, 2)
out_gemm_kernel(const float* __restrict__ Wo,
                const float* __restrict__ bo,
                float* __restrict__ Y)
{
    __shared__ uint4 Ah[2][512];
    __shared__ uint2 Bh[2][1024];

    const int tid = threadIdx.x, lane = tid & 31, wid = tid >> 5;
    const int wm = wid >> 1, wn = wid & 1;
    const int row0 = blockIdx.y * 128, col0 = blockIdx.x * 128;
    const int r8 = lane >> 2, cc = lane & 3, cx = cc ^ (r8 & 3);
    const int lr = tid >> 1, lk = (tid & 1) << 3;

    const float* Ab = g_O + (size_t)(row0 + lr) * HIDDEN + lk;
    const float* Bb = Wo  + (size_t)(col0 + lr) * HIDDEN + lk;

    float ea[8], eb[8];
    ldrow(Ab, ea); ldrow(Bb, eb);
    packA32(ea, Ah[0], tid);
    packB32_nt(eb, Bh[0], tid);
    __syncthreads();

    float d[2][8][4] = {};
    for (int k0 = 0; k0 < HIDDEN; k0 += 16) {
        const int cur = (k0 >> 4) & 1, nxt = cur ^ 1;
        const bool more = (k0 + 16) < HIDDEN;
        if (more) { ldrow(Ab + k0 + 16, ea); ldrow(Bb + k0 + 16, eb); }

        #pragma unroll
        for (int k8 = 0; k8 < 2; ++k8) {
            uint4 ah[2];
            #pragma unroll
            for (int mt = 0; mt < 2; ++mt)
                ah[mt] = Ah[cur][AIDX(wm * 2 + mt, k8, r8, cx)];
            #pragma unroll
            for (int nt = 0; nt < 8; ++nt) {
                const uint2 bv = Bh[cur][BIDX(wn * 8 + nt, k8, r8, cc)];
                #pragma unroll
                for (int mt = 0; mt < 2; ++mt)
                    mma8(d[mt][nt], ah[mt], bv);
            }
        }
        if (more) {
            packA32(ea, Ah[nxt], tid);
            packB32_nt(eb, Bh[nxt], tid);
        }
        __syncthreads();
    }

    const int g = lane >> 2, t2 = (lane & 3) << 1;
    #pragma unroll
    for (int mt = 0; mt < 2; ++mt) {
        const int rA = row0 + (wm * 2 + mt) * 16 + g;
        const int rB = rA + 8;
        #pragma unroll
        for (int nt = 0; nt < 8; ++nt) {
            const int col = col0 + (wn * 8 + nt) * 8 + t2;
            const float b0 = bo[col], b1 = bo[col + 1];
            *(float2*)&Y[(size_t)rA * HIDDEN + col] =
                make_float2(d[mt][nt][0] + b0, d[mt][nt][1] + b1);
            *(float2*)&Y[(size_t)rB * HIDDEN + col] =
                make_float2(d[mt][nt][2] + b0, d[mt][nt][3] + b1);
        }
    }
}

// ---------------------------------------------------------------------------
// Launch. Counters zeroed via capturable cudaMemsetAsync; V projection on s_v;
// scores->select->av split into two bh-halves (s_b pipelines half B).
// ---------------------------------------------------------------------------
extern "C" void kernel_launch(void* const* d_in, const int* in_sizes, int n_in,
                              void* d_out, int out_size)
{
    const float* x   = (const float*)d_in[0];
    const float* Wq  = (const float*)d_in[1];
    const float* Wk  = (const float*)d_in[2];
    const float* Wv  = (const float*)d_in[3];
    const float* Wo  = (const float*)d_in[4];
    const float* bo  = (const float*)d_in[5];
    const float* thr = (const float*)d_in[6];
    float* out = (float*)d_out;

    static cudaStream_t s_v = nullptr, s_b = nullptr;
    static cudaEvent_t  ev_fork = nullptr, ev_v = nullptr,
                        ev_qk = nullptr, ev_b = nullptr;
    static void *p_cnt = nullptr, *p_maxk = nullptr, *p_nslow = nullptr;
    if (s_v == nullptr) {
        cudaStreamCreateWithFlags(&s_v, cudaStreamNonBlocking);
        cudaStreamCreateWithFlags(&s_b, cudaStreamNonBlocking);
        cudaEventCreateWithFlags(&ev_fork, cudaEventDisableTiming);
        cudaEventCreateWithFlags(&ev_v,    cudaEventDisableTiming);
        cudaEventCreateWithFlags(&ev_qk,   cudaEventDisableTiming);
        cudaEventCreateWithFlags(&ev_b,    cudaEventDisableTiming);
        cudaGetSymbolAddress(&p_cnt,   g_cnt);
        cudaGetSymbolAddress(&p_maxk,  g_maxk);
        cudaGetSymbolAddress(&p_nslow, g_nslow);
    }

    const int HB = BH / 2;   // 16 heads per half

    // zero per-row counters (capturable async memsets on main stream)
    cudaMemsetAsync(p_cnt,   0, NROWS * sizeof(unsigned), 0);
    cudaMemsetAsync(p_maxk,  0, NROWS * sizeof(unsigned), 0);
    cudaMemsetAsync(p_nslow, 0, 2 * sizeof(unsigned), 0);

    cudaEventRecord(ev_fork, 0);
    cudaStreamWaitEvent(s_v, ev_fork, 0);

    // V projection on s_v
    dim3 gv(HIDDEN / 128, MROWS / 128, 1);
    qkv_gemm_kernel<<<gv, 256, 0, s_v>>>(x, Wq, Wk, Wv, 2);
    cudaEventRecord(ev_v, s_v);

    // Q,K projections on main
    dim3 gqk(HIDDEN / 128, MROWS / 128, 2);
    qkv_gemm_kernel<<<gqk, 256>>>(x, Wq, Wk, Wv, 0);
    cudaEventRecord(ev_qk, 0);

    // ---- half B chain on s_b ----
    cudaStreamWaitEvent(s_b, ev_qk, 0);
    dim3 gs(SEQ / 128, SEQ / 128, HB);
    scores_gemm_kernel<<<gs, 256, 0, s_b>>>(thr, HB);
    select_fast_kernel<<<HROWS / 256, 256, 0, s_b>>>(HROWS, 1);
    select_slow_kernel<<<32, 256, 0, s_b>>>(1);
    cudaStreamWaitEvent(s_b, ev_v, 0);
    dim3 gav(SEQ / 128, HB);
    av_gemm_kernel<<<gav, 256, 0, s_b>>>(thr, HB);
    cudaEventRecord(ev_b, s_b);

    // ---- half A chain on main ----
    scores_gemm_kernel<<<gs, 256>>>(thr, 0);
    select_fast_kernel<<<HROWS / 256, 256>>>(0, 0);
    select_slow_kernel<<<32, 256>>>(0);
    cudaStreamWaitEvent(0, ev_v, 0);
    av_gemm_kernel<<<gav, 256>>>(thr, 0);

    // join half B, then output projection
    cudaStreamWaitEvent(0, ev_b, 0);
    dim3 go(HIDDEN / 128, MROWS / 128);
    out_gemm_kernel<<<go, 256>>>(Wo, bo, out);
}

// round 13
// speedup vs baseline: 2.2450x; 1.0941x over previous
#include <cuda_runtime.h>
#include <cuda_bf16.h>
#include <math.h>

#define HIDDEN   1024
#define HEADS    16
#define HEAD_DIM 64
#define BATCH    2
#define SEQ      2048
#define MROWS    (BATCH*SEQ)     // 4096
#define BH       (BATCH*HEADS)   // 32
#define KKEEP    1024
#define NROWS    (BH*SEQ)        // 65536
#define HROWS    (NROWS/2)

// ---------------------------------------------------------------------------
// Scratch (device globals; no runtime allocation allowed)
// ---------------------------------------------------------------------------
__device__ float    g_Q[(size_t)BH*SEQ*HEAD_DIM];
__device__ float    g_K[(size_t)BH*SEQ*HEAD_DIM];
__device__ float    g_V[(size_t)BH*SEQ*HEAD_DIM];
__device__ float    g_O[(size_t)MROWS*HIDDEN];
__device__ float    g_S[(size_t)BH*SEQ*SEQ];      // fp32 scores, 512MB
__device__ float4   g_par[NROWS];                 // (kthbits, m~, 0, 0)
__device__ unsigned g_cnt[NROWS];
__device__ unsigned g_maxk[NROWS];
__device__ unsigned g_nslow[2];
__device__ unsigned g_slowlist[2][HROWS];

// ---------------------------------------------------------------------------
// MMA plumbing
// ---------------------------------------------------------------------------
__device__ __forceinline__ unsigned f2tf32(float f) {
    unsigned u;
    asm("cvt.rna.tf32.f32 %0, %1;" : "=r"(u) : "f"(f));
    return u;
}
__device__ __forceinline__ void mma8(float d[4], const uint4& a, const uint2& b) {
    asm("mma.sync.aligned.m16n8k8.row.col.f32.tf32.tf32.f32 "
        "{%0,%1,%2,%3},{%4,%5,%6,%7},{%8,%9},{%0,%1,%2,%3};"
        : "+f"(d[0]), "+f"(d[1]), "+f"(d[2]), "+f"(d[3])
        : "r"(a.x), "r"(a.y), "r"(a.z), "r"(a.w), "r"(b.x), "r"(b.y));
}
__device__ __forceinline__ void mma16(float d[4], const uint4& a, const uint2& b) {
    asm("mma.sync.aligned.m16n8k16.row.col.f32.bf16.bf16.f32 "
        "{%0,%1,%2,%3},{%4,%5,%6,%7},{%8,%9},{%0,%1,%2,%3};"
        : "+f"(d[0]), "+f"(d[1]), "+f"(d[2]), "+f"(d[3])
        : "r"(a.x), "r"(a.y), "r"(a.z), "r"(a.w), "r"(b.x), "r"(b.y));
}

// tf32 frag indexers, chunk16 (2 k8) — out_gemm
__device__ __forceinline__ int AIDX(int mt, int k8, int r8, int cx) {
    return ((((mt << 1) + k8) << 3) + r8) * 4 + cx;
}
__device__ __forceinline__ int BIDX(int nt, int k8, int n8, int c) {
    return ((((nt << 1) + k8) << 3) + n8) * 4 + c;
}
// tf32 frag indexers, chunk32 (4 k8) — av kernel
__device__ __forceinline__ int AIDX4(int mt, int k8, int r8, int cx) {
    return ((((mt << 2) + k8) << 3) + r8) * 4 + cx;
}
__device__ __forceinline__ int BIDX4(int nt, int k8, int n8, int c) {
    return ((((nt << 2) + k8) << 3) + n8) * 4 + c;
}
// bf16 frag indexers (k16 granularity)
__device__ __forceinline__ int AIDXb(int mt, int r8, int cx) {
    return ((mt << 3) + r8) * 4 + cx;
}
__device__ __forceinline__ int BIDXb(int nt, int n8, int c) {
    return ((nt << 3) + n8) * 4 + c;
}

__device__ __forceinline__ void ldrow(const float* __restrict__ p, float e[8]) {
    float4 a = *(const float4*)p;
    float4 b = *(const float4*)(p + 4);
    e[0]=a.x; e[1]=a.y; e[2]=a.z; e[3]=a.w;
    e[4]=b.x; e[5]=b.y; e[6]=b.z; e[7]=b.w;
}

__device__ __forceinline__ void bsplit(float e, unsigned short& h, unsigned short& l) {
    __nv_bfloat16 bh = __float2bfloat16(e);
    h = __bfloat16_as_ushort(bh);
    l = __bfloat16_as_ushort(__float2bfloat16(e - __bfloat162float(bh)));
}

// ---- bf16 packs (hi + lo) ----
__device__ __forceinline__ void packA16(const float e[8], uint4* Ah, uint4* Al, int tid)
{
    const int lr = tid >> 1, kh = tid & 1;
    const int mt = lr >> 4, rr = lr & 15, r8 = rr & 7, rh = rr >> 3;
    const int comp = rh + (kh << 1);
    #pragma unroll
    for (int c = 0; c < 4; ++c) {
        unsigned short h0, l0, h1, l1;
        bsplit(e[2*c],   h0, l0);
        bsplit(e[2*c+1], h1, l1);
        const int idx = AIDXb(mt, r8, c ^ (r8 & 3));
        ((unsigned*)&Ah[idx])[comp] = (unsigned)h0 | ((unsigned)h1 << 16);
        ((unsigned*)&Al[idx])[comp] = (unsigned)l0 | ((unsigned)l1 << 16);
    }
}
__device__ __forceinline__ void packB16(const float e[8], uint2* Bh, uint2* Bl, int tid)
{
    const int ln = tid >> 1, kh = tid & 1;
    const int nt = ln >> 3, n8 = ln & 7;
    #pragma unroll
    for (int c = 0; c < 4; ++c) {
        unsigned short h0, l0, h1, l1;
        bsplit(e[2*c],   h0, l0);
        bsplit(e[2*c+1], h1, l1);
        const int idx = BIDXb(nt, n8, c);
        ((unsigned*)&Bh[idx])[kh] = (unsigned)h0 | ((unsigned)h1 << 16);
        ((unsigned*)&Bl[idx])[kh] = (unsigned)l0 | ((unsigned)l1 << 16);
    }
}

// ---- tf32 packs ----
__device__ __forceinline__ void packA32(const float e[8], uint4* Ah, int tid)
{
    const int lr = tid >> 1;
    const int mt = lr >> 4, rr = lr & 15, r8 = rr & 7, rh = rr >> 3, k8 = tid & 1;
    #pragma unroll
    for (int j = 0; j < 8; ++j) {
        const int c = j & 3, ch = (j >> 2) & 1;
        const int comp = rh + (ch << 1);
        ((unsigned*)&Ah[AIDX(mt, k8, r8, c ^ (r8 & 3))])[comp] = f2tf32(e[j]);
    }
}
__device__ __forceinline__ unsigned f2u(float f) {
    unsigned b = __float_as_uint(f);
    return (b & 0x80000000u) ? ~b : (b | 0x80000000u);
}
__device__ __forceinline__ float u2f(unsigned u) {
    unsigned b = (u & 0x80000000u) ? (u & 0x7FFFFFFFu) : ~u;
    return __uint_as_float(b);
}
// AV chunk32 A pack: 8 values at k8 slot (gate+exp fused)
__device__ __forceinline__ void packA_av4(const float e[8], uint4* Ah, int lr, int k8,
                                          float gate, float m, float& psum)
{
    const int mt = lr >> 4, rr = lr & 15, r8 = rr & 7, rh = rr >> 3;
    #pragma unroll
    for (int j = 0; j < 8; ++j) {
        const float pe = (e[j] >= gate) ? __expf(e[j] - m) : 0.f;
        psum += pe;
        const int c = j & 3, ch = (j >> 2) & 1;
        const int comp = rh + (ch << 1);
        ((unsigned*)&Ah[AIDX4(mt, k8, r8, c ^ (r8 & 3))])[comp] = f2tf32(pe);
    }
}
__device__ __forceinline__ void packB32_nt(const float e[8], uint2* Bh, int tid)
{
    const int ln = tid >> 1;
    const int nt = ln >> 3, n8 = ln & 7, k8 = tid & 1;
    #pragma unroll
    for (int j = 0; j < 8; ++j) {
        const int c = j & 3, ph = (j >> 2) & 1;
        ((unsigned*)&Bh[BIDX(nt, k8, n8, c)])[ph] = f2tf32(e[j]);
    }
}
// AV chunk32 V pack: thread owns one k-row (vkr of 32), 8 consecutive n
__device__ __forceinline__ void packB32_nn4(const float e[8], uint2* Bh, int vkr, int vnc)
{
    const int k8 = vkr >> 3, kv = vkr & 7;
    const int c = kv & 3, ph = kv >> 2;
    #pragma unroll
    for (int j = 0; j < 8; ++j) {
        const int n = vnc + j;
        ((unsigned*)&Bh[BIDX4(n >> 3, k8, n & 7, c)])[ph] = f2tf32(e[j]);
    }
}

// ---------------------------------------------------------------------------
// QKV projections (bf16x3, pipelined) -> Q/K/V in [bh, s, d]
// ---------------------------------------------------------------------------
__global__ void __launch_bounds__(256, 2)
qkv_gemm_kernel(const float* __restrict__ x,
                const float* __restrict__ Wq,
                const float* __restrict__ Wk,
                const float* __restrict__ Wv,
                int zbase)
{
    __shared__ uint4 Ah[2][256], Al[2][256];
    __shared__ uint2 Bh[2][512], Bl[2][512];

    const int z = blockIdx.z + zbase;
    const float* W = (z == 0) ? Wq : (z == 1 ? Wk : Wv);
    float*       C = (z == 0) ? g_Q : (z == 1 ? g_K : g_V);

    const int tid = threadIdx.x, lane = tid & 31, wid = tid >> 5;
    const int wm = wid >> 1, wn = wid & 1;
    const int row0 = blockIdx.y * 128, col0 = blockIdx.x * 128;
    const int r8 = lane >> 2, cc = lane & 3, cx = cc ^ (r8 & 3);
    const int lr = tid >> 1, lk = (tid & 1) << 3;

    const float* Ab = x + (size_t)(row0 + lr) * HIDDEN + lk;
    const float* Bb = W + (size_t)(col0 + lr) * HIDDEN + lk;

    float ea[8], eb[8];
    ldrow(Ab, ea); ldrow(Bb, eb);
    packA16(ea, Ah[0], Al[0], tid);
    packB16(eb, Bh[0], Bl[0], tid);
    __syncthreads();

    float d[2][8][4] = {};
    for (int k0 = 0; k0 < HIDDEN; k0 += 16) {
        const int cur = (k0 >> 4) & 1, nxt = cur ^ 1;
        const bool more = (k0 + 16) < HIDDEN;
        if (more) { ldrow(Ab + k0 + 16, ea); ldrow(Bb + k0 + 16, eb); }

        uint4 ah[2], al[2];
        #pragma unroll
        for (int mt = 0; mt < 2; ++mt) {
            ah[mt] = Ah[cur][AIDXb(wm * 2 + mt, r8, cx)];
            al[mt] = Al[cur][AIDXb(wm * 2 + mt, r8, cx)];
        }
        #pragma unroll
        for (int nt = 0; nt < 8; ++nt) {
            const int bi = BIDXb(wn * 8 + nt, r8, cc);
            const uint2 bhv = Bh[cur][bi], blv = Bl[cur][bi];
            #pragma unroll
            for (int mt = 0; mt < 2; ++mt) {
                mma16(d[mt][nt], ah[mt], bhv);
                mma16(d[mt][nt], ah[mt], blv);
                mma16(d[mt][nt], al[mt], bhv);
            }
        }
        if (more) {
            packA16(ea, Ah[nxt], Al[nxt], tid);
            packB16(eb, Bh[nxt], Bl[nxt], tid);
        }
        __syncthreads();
    }

    const int g = lane >> 2, t2 = (lane & 3) << 1;
    #pragma unroll
    for (int mt = 0; mt < 2; ++mt) {
        const int rA = row0 + (wm * 2 + mt) * 16 + g;
        const int rB = rA + 8;
        const int bA = rA >> 11, sA = rA & (SEQ - 1);
        const int bB = rB >> 11, sB = rB & (SEQ - 1);
        #pragma unroll
        for (int nt = 0; nt < 8; ++nt) {
            const int col = col0 + (wn * 8 + nt) * 8 + t2;
            const int h = col >> 6, dd = col & 63;
            *(float2*)&C[(((size_t)(bA * HEADS + h) * SEQ) + sA) * HEAD_DIM + dd] =
                make_float2(d[mt][nt][0], d[mt][nt][1]);
            *(float2*)&C[(((size_t)(bB * HEADS + h) * SEQ) + sB) * HEAD_DIM + dd] =
                make_float2(d[mt][nt][2], d[mt][nt][3]);
        }
    }
}

// ---------------------------------------------------------------------------
// Scores (bf16x3, pipelined): writes fp32 S; per-row cnt/max via atomics
// ---------------------------------------------------------------------------
__global__ void __launch_bounds__(256, 2)
scores_gemm_kernel(const float* __restrict__ thr_ptr, int bh_base)
{
    __shared__ uint4 Ah[2][256], Al[2][256];
    __shared__ uint2 Bh[2][512], Bl[2][512];

    const int bh = blockIdx.z + bh_base;
    const float* Qb = g_Q + (size_t)bh * SEQ * HEAD_DIM;
    const float* Kb = g_K + (size_t)bh * SEQ * HEAD_DIM;
    float*       Sb = g_S + (size_t)bh * SEQ * SEQ;

    const int tid = threadIdx.x, lane = tid & 31, wid = tid >> 5;
    const int wm = wid >> 1, wn = wid & 1;
    const int row0 = blockIdx.y * 128, col0 = blockIdx.x * 128;
    const int r8 = lane >> 2, cc = lane & 3, cx = cc ^ (r8 & 3);
    const int lr = tid >> 1, lk = (tid & 1) << 3;

    const float* Ab = Qb + (size_t)(row0 + lr) * HEAD_DIM + lk;
    const float* Bb = Kb + (size_t)(col0 + lr) * HEAD_DIM + lk;

    float ea[8], eb[8];
    ldrow(Ab, ea); ldrow(Bb, eb);
    packA16(ea, Ah[0], Al[0], tid);
    packB16(eb, Bh[0], Bl[0], tid);
    __syncthreads();

    float d[2][8][4] = {};
    #pragma unroll
    for (int k0 = 0; k0 < HEAD_DIM; k0 += 16) {
        const int cur = (k0 >> 4) & 1, nxt = cur ^ 1;
        const bool more = (k0 + 16) < HEAD_DIM;
        if (more) { ldrow(Ab + k0 + 16, ea); ldrow(Bb + k0 + 16, eb); }

        uint4 ah[2], al[2];
        #pragma unroll
        for (int mt = 0; mt < 2; ++mt) {
            ah[mt] = Ah[cur][AIDXb(wm * 2 + mt, r8, cx)];
            al[mt] = Al[cur][AIDXb(wm * 2 + mt, r8, cx)];
        }
        #pragma unroll
        for (int nt = 0; nt < 8; ++nt) {
            const int bi = BIDXb(wn * 8 + nt, r8, cc);
            const uint2 bhv = Bh[cur][bi], blv = Bl[cur][bi];
            #pragma unroll
            for (int mt = 0; mt < 2; ++mt) {
                mma16(d[mt][nt], ah[mt], bhv);
                mma16(d[mt][nt], ah[mt], blv);
                mma16(d[mt][nt], al[mt], bhv);
            }
        }
        if (more) {
            packA16(ea, Ah[nxt], Al[nxt], tid);
            packB16(eb, Bh[nxt], Bl[nxt], tid);
        }
        __syncthreads();
    }

    const float thrv = fminf(fmaxf(*thr_ptr, 0.f), 1.f);
    const unsigned thr16 = (f2u(thrv) + 0xFFFFu) >> 16;

    const int g = lane >> 2, t2 = (lane & 3) << 1;
    #pragma unroll
    for (int mt = 0; mt < 2; ++mt) {
        const int qA = row0 + (wm * 2 + mt) * 16 + g;
        const int qB = qA + 8;
        unsigned cA = 0, cB = 0, mA = 0, mB = 0;
        #pragma unroll
        for (int nt = 0; nt < 8; ++nt) {
            const int col = col0 + (wn * 8 + nt) * 8 + t2;
            const float a0 = d[mt][nt][0] * 0.125f, a1 = d[mt][nt][1] * 0.125f;
            const float b0 = d[mt][nt][2] * 0.125f, b1 = d[mt][nt][3] * 0.125f;
            *(float2*)&Sb[(size_t)qA * SEQ + col] = make_float2(a0, a1);
            *(float2*)&Sb[(size_t)qB * SEQ + col] = make_float2(b0, b1);
            const unsigned kA0 = f2u(a0) >> 16, kA1 = f2u(a1) >> 16;
            const unsigned kB0 = f2u(b0) >> 16, kB1 = f2u(b1) >> 16;
            cA += (kA0 >= thr16) + (kA1 >= thr16);
            cB += (kB0 >= thr16) + (kB1 >= thr16);
            mA = max(mA, max(kA0, kA1));
            mB = max(mB, max(kB0, kB1));
        }
        const size_t rgA = (size_t)bh * SEQ + qA;
        const size_t rgB = (size_t)bh * SEQ + qB;
        atomicAdd(&g_cnt[rgA], cA);
        atomicAdd(&g_cnt[rgB], cB);
        atomicMax(&g_maxk[rgA], mA);
        atomicMax(&g_maxk[rgB], mB);
    }
}

// ---------------------------------------------------------------------------
// select_fast: one thread per row; slow rows appended to per-half list
// ---------------------------------------------------------------------------
__global__ void select_fast_kernel(int row_base, int half)
{
    const int row = row_base + blockIdx.x * blockDim.x + threadIdx.x;
    const unsigned cnt = g_cnt[row];
    const unsigned mk  = g_maxk[row];
    if (cnt < (unsigned)KKEEP) {
        g_par[row] = make_float4(__uint_as_float(0x007FFFFFu),  // orderable(-inf)
                                 u2f(mk << 16), 0.f, 0.f);
    } else {
        const unsigned i = atomicAdd(&g_nslow[half], 1u);
        g_slowlist[half][i] = (unsigned)row;
    }
}

// ---------------------------------------------------------------------------
// select_slow: persistent blocks drain the slow list (exact 2-pass radix)
// ---------------------------------------------------------------------------
__global__ void select_slow_kernel(int half)
{
    __shared__ unsigned hist[256];
    __shared__ unsigned wsum[8];
    __shared__ unsigned s_b;
    __shared__ int      s_kk;

    const int tid = threadIdx.x;
    const int lane = tid & 31, wrp = tid >> 5;
    const unsigned n = *((volatile unsigned*)&g_nslow[half]);

    for (unsigned it = blockIdx.x; it < n; it += gridDim.x) {
        const int row = (int)g_slowlist[half][it];
        const float* Srow = g_S + (size_t)row * SEQ;

        float4 v0 = ((const float4*)Srow)[tid];
        float4 v1 = ((const float4*)Srow)[256 + tid];
        const float sv[8] = {v0.x, v0.y, v0.z, v0.w, v1.x, v1.y, v1.z, v1.w};
        unsigned k[8];
        #pragma unroll
        for (int t = 0; t < 8; ++t) k[t] = f2u(sv[t]) >> 16;

        int kk = KKEEP;
        unsigned b1;
        hist[tid] = 0;
        __syncthreads();
        #pragma unroll
        for (int t = 0; t < 8; ++t) {
            const unsigned bin = k[t] >> 8;
            const unsigned peers = __match_any_sync(0xFFFFFFFFu, bin);
            if (lane == (__ffs(peers) - 1))
                atomicAdd(&hist[bin], (unsigned)__popc(peers));
        }
        __syncthreads();
        {
            unsigned myc = hist[tid];
            unsigned cum = myc;
            #pragma unroll
            for (int o = 1; o < 32; o <<= 1) {
                unsigned g2 = __shfl_down_sync(0xFFFFFFFFu, cum, o);
                if (lane + o < 32) cum += g2;
            }
            if (lane == 0) wsum[wrp] = cum;
            __syncthreads();
            unsigned above = 0;
            #pragma unroll
            for (int w = 0; w < 8; ++w) if (w > wrp) above += wsum[w];
            cum += above;
            if (cum >= (unsigned)kk && (cum - myc) < (unsigned)kk) {
                s_b  = (unsigned)tid;
                s_kk = kk - (int)(cum - myc);
            }
        }
        __syncthreads();
        b1 = s_b;
        kk = s_kk;
        __syncthreads();

        hist[tid] = 0;
        __syncthreads();
        #pragma unroll
        for (int t = 0; t < 8; ++t) {
            const bool ok = (k[t] >> 8) == b1;
            const unsigned mok = __ballot_sync(0xFFFFFFFFu, ok);
            if (mok) {
                const unsigned bin = k[t] & 0xFFu;
                const unsigned key = ok ? bin : (256u + (unsigned)lane);
                const unsigned peers = __match_any_sync(0xFFFFFFFFu, key);
                if (ok && lane == (__ffs(peers) - 1))
                    atomicAdd(&hist[bin], (unsigned)__popc(peers));
            }
        }
        __syncthreads();
        {
            unsigned myc = hist[tid];
            unsigned cum = myc;
            #pragma unroll
            for (int o = 1; o < 32; o <<= 1) {
                unsigned g2 = __shfl_down_sync(0xFFFFFFFFu, cum, o);
                if (lane + o < 32) cum += g2;
            }
            if (lane == 0) wsum[wrp] = cum;
            __syncthreads();
            unsigned above = 0;
            #pragma unroll
            for (int w = 0; w < 8; ++w) if (w > wrp) above += wsum[w];
            cum += above;
            if (cum >= (unsigned)kk && (cum - myc) < (unsigned)kk)
                s_b = (b1 << 8) | (unsigned)tid;
        }
        __syncthreads();

        if (tid == 0) {
            const unsigned kth16 = s_b;
            g_par[row] = make_float4(__uint_as_float(kth16 << 16),
                                     u2f(g_maxk[row] << 16), 0.f, 0.f);
        }
        __syncthreads();
    }
}

// ---------------------------------------------------------------------------
// AV (tf32 x1, fused gate+softmax+sum): chunk K=32, round-6 warp layout.
// ---------------------------------------------------------------------------
__global__ void __launch_bounds__(256, 2)
av_gemm_kernel(const float* __restrict__ thr_ptr, int bh_base)
{
    __shared__ uint4 Ah[2][1024];   // 128q x 32k tf32 fragments
    __shared__ uint2 Bh[2][1024];   // 32k x 64n tf32 fragments
    __shared__ float rowsum[128];

    const int bh   = blockIdx.y + bh_base;
    const int row0 = blockIdx.x * 128;
    const float* Sb = g_S + (size_t)bh * SEQ * SEQ;
    const float* Vb = g_V + (size_t)bh * SEQ * HEAD_DIM;

    const int tid = threadIdx.x, lane = tid & 31, wid = tid >> 5;
    const int wm = wid >> 1, wn = wid & 1;
    const int r8 = lane >> 2, cc = lane & 3, cx = cc ^ (r8 & 3);
    // S loader: 2 threads per row, 16 k each
    const int lr = tid >> 1, lk2 = (tid & 1) << 4;
    const int k8base = (tid & 1) << 1;           // 0 or 2
    // V loader: 8 threads per k-row, 8 n each
    const int vkr = tid >> 3, vnc = (tid & 7) << 3;

    const float4 par = g_par[(size_t)bh * SEQ + row0 + lr];
    const float thr  = fminf(fmaxf(*thr_ptr, 0.f), 1.f);
    const float gate = fmaxf(u2f(__float_as_uint(par.x)), thr);
    const float mrow = par.y;

    const float* Ab = Sb + (size_t)(row0 + lr) * SEQ + lk2;
    const float* Bb = Vb + (size_t)vkr * HEAD_DIM + vnc;

    float psum = 0.f;
    float ea0[8], ea1[8], evb[8];
    ldrow(Ab, ea0); ldrow(Ab + 8, ea1);
    ldrow(Bb, evb);
    packA_av4(ea0, Ah[0], lr, k8base,     gate, mrow, psum);
    packA_av4(ea1, Ah[0], lr, k8base + 1, gate, mrow, psum);
    packB32_nn4(evb, Bh[0], vkr, vnc);
    __syncthreads();

    float d[2][4][4] = {};
    for (int k0 = 0; k0 < SEQ; k0 += 32) {
        const int cur = (k0 >> 5) & 1, nxt = cur ^ 1;
        const bool more = (k0 + 32) < SEQ;
        if (more) {
            ldrow(Ab + k0 + 32, ea0);
            ldrow(Ab + k0 + 40, ea1);
            ldrow(Bb + (size_t)(k0 + 32) * HEAD_DIM, evb);
        }

        #pragma unroll
        for (int k8 = 0; k8 < 4; ++k8) {
            uint4 ah[2];
            #pragma unroll
            for (int mt = 0; mt < 2; ++mt)
                ah[mt] = Ah[cur][AIDX4(wm * 2 + mt, k8, r8, cx)];
            #pragma unroll
            for (int nt = 0; nt < 4; ++nt) {
                const uint2 bv = Bh[cur][BIDX4(wn * 4 + nt, k8, r8, cc)];
                #pragma unroll
                for (int mt = 0; mt < 2; ++mt)
                    mma8(d[mt][nt], ah[mt], bv);
            }
        }
        if (more) {
            packA_av4(ea0, Ah[nxt], lr, k8base,     gate, mrow, psum);
            packA_av4(ea1, Ah[nxt], lr, k8base + 1, gate, mrow, psum);
            packB32_nn4(evb, Bh[nxt], vkr, vnc);
        }
        __syncthreads();
    }

    {
        const float tot = psum + __shfl_xor_sync(0xFFFFFFFFu, psum, 1);
        if ((tid & 1) == 0) rowsum[lr] = tot;
    }
    __syncthreads();

    const int b = bh >> 4, h = bh & 15;
    const int g = lane >> 2, t2 = (lane & 3) << 1;
    #pragma unroll
    for (int mt = 0; mt < 2; ++mt) {
        const int qA = row0 + (wm * 2 + mt) * 16 + g;
        const int qB = qA + 8;
        const float invA = 1.f / rowsum[qA - row0];
        const float invB = 1.f / rowsum[qB - row0];
        #pragma unroll
        for (int nt = 0; nt < 4; ++nt) {
            const int col = (wn * 4 + nt) * 8 + t2;
            *(float2*)&g_O[(((size_t)b * SEQ + qA) * HIDDEN) + h * HEAD_DIM + col] =
                make_float2(d[mt][nt][0] * invA, d[mt][nt][1] * invA);
            *(float2*)&g_O[(((size_t)b * SEQ + qB) * HIDDEN) + h * HEAD_DIM + col] =
                make_float2(d[mt][nt][2] * invB, d[mt][nt][3] * invB);
        }
    }
}

// ---------------------------------------------------------------------------
// Output projection (tf32 x1, pipelined): Y = g_O @ Wo^T + bo  (batch slice)
// ---------------------------------------------------------------------------
__global__ void __launch_bounds__(256, 2)
out_gemm_kernel(const float* __restrict__ Wo,
                const float* __restrict__ bo,
                float* __restrict__ Y,
                int row_base)
{
    __shared__ uint4 Ah[2][512];
    __shared__ uint2 Bh[2][1024];

    const int tid = threadIdx.x, lane = tid & 31, wid = tid >> 5;
    const int wm = wid >> 1, wn = wid & 1;
    const int row0 = row_base + blockIdx.y * 128, col0 = blockIdx.x * 128;
    const int r8 = lane >> 2, cc = lane & 3, cx = cc ^ (r8 & 3);
    const int lr = tid >> 1, lk = (tid & 1) << 3;

    const float* Ab = g_O + (size_t)(row0 + lr) * HIDDEN + lk;
    const float* Bb = Wo  + (size_t)(col0 + lr) * HIDDEN + lk;

    float ea[8], eb[8];
    ldrow(Ab, ea); ldrow(Bb, eb);
    packA32(ea, Ah[0], tid);
    packB32_nt(eb, Bh[0], tid);
    __syncthreads();

    float d[2][8][4] = {};
    for (int k0 = 0; k0 < HIDDEN; k0 += 16) {
        const int cur = (k0 >> 4) & 1, nxt = cur ^ 1;
        const bool more = (k0 + 16) < HIDDEN;
        if (more) { ldrow(Ab + k0 + 16, ea); ldrow(Bb + k0 + 16, eb); }

        #pragma unroll
        for (int k8 = 0; k8 < 2; ++k8) {
            uint4 ah[2];
            #pragma unroll
            for (int mt = 0; mt < 2; ++mt)
                ah[mt] = Ah[cur][AIDX(wm * 2 + mt, k8, r8, cx)];
            #pragma unroll
            for (int nt = 0; nt < 8; ++nt) {
                const uint2 bv = Bh[cur][BIDX(wn * 8 + nt, k8, r8, cc)];
                #pragma unroll
                for (int mt = 0; mt < 2; ++mt)
                    mma8(d[mt][nt], ah[mt], bv);
            }
        }
        if (more) {
            packA32(ea, Ah[nxt], tid);
            packB32_nt(eb, Bh[nxt], tid);
        }
        __syncthreads();
    }

    const int g = lane >> 2, t2 = (lane & 3) << 1;
    #pragma unroll
    for (int mt = 0; mt < 2; ++mt) {
        const int rA = row0 + (wm * 2 + mt) * 16 + g;
        const int rB = rA + 8;
        #pragma unroll
        for (int nt = 0; nt < 8; ++nt) {
            const int col = col0 + (wn * 8 + nt) * 8 + t2;
            const float b0 = bo[col], b1 = bo[col + 1];
            *(float2*)&Y[(size_t)rA * HIDDEN + col] =
                make_float2(d[mt][nt][0] + b0, d[mt][nt][1] + b1);
            *(float2*)&Y[(size_t)rB * HIDDEN + col] =
                make_float2(d[mt][nt][2] + b0, d[mt][nt][3] + b1);
        }
    }
}

// ---------------------------------------------------------------------------
// Launch. Half A = batch 0 (bh 0..15), half B = batch 1 (bh 16..31); out is
// split by batch and chained per half. Resources created once outside capture.
// ---------------------------------------------------------------------------
extern "C" void kernel_launch(void* const* d_in, const int* in_sizes, int n_in,
                              void* d_out, int out_size)
{
    const float* x   = (const float*)d_in[0];
    const float* Wq  = (const float*)d_in[1];
    const float* Wk  = (const float*)d_in[2];
    const float* Wv  = (const float*)d_in[3];
    const float* Wo  = (const float*)d_in[4];
    const float* bo  = (const float*)d_in[5];
    const float* thr = (const float*)d_in[6];
    float* out = (float*)d_out;

    static cudaStream_t s_v = nullptr, s_b = nullptr;
    static cudaEvent_t  ev_fork = nullptr, ev_v = nullptr,
                        ev_qk = nullptr, ev_b = nullptr;
    static void *p_cnt = nullptr, *p_maxk = nullptr, *p_nslow = nullptr;
    if (s_v == nullptr) {
        cudaStreamCreateWithFlags(&s_v, cudaStreamNonBlocking);
        cudaStreamCreateWithFlags(&s_b, cudaStreamNonBlocking);
        cudaEventCreateWithFlags(&ev_fork, cudaEventDisableTiming);
        cudaEventCreateWithFlags(&ev_v,    cudaEventDisableTiming);
        cudaEventCreateWithFlags(&ev_qk,   cudaEventDisableTiming);
        cudaEventCreateWithFlags(&ev_b,    cudaEventDisableTiming);
        cudaGetSymbolAddress(&p_cnt,   g_cnt);
        cudaGetSymbolAddress(&p_maxk,  g_maxk);
        cudaGetSymbolAddress(&p_nslow, g_nslow);
    }

    const int HB = BH / 2;   // 16 heads per half

    cudaMemsetAsync(p_cnt,   0, NROWS * sizeof(unsigned), 0);
    cudaMemsetAsync(p_maxk,  0, NROWS * sizeof(unsigned), 0);
    cudaMemsetAsync(p_nslow, 0, 2 * sizeof(unsigned), 0);

    cudaEventRecord(ev_fork, 0);
    cudaStreamWaitEvent(s_v, ev_fork, 0);

    // V projection on s_v
    dim3 gv(HIDDEN / 128, MROWS / 128, 1);
    qkv_gemm_kernel<<<gv, 256, 0, s_v>>>(x, Wq, Wk, Wv, 2);
    cudaEventRecord(ev_v, s_v);

    // Q,K projections on main
    dim3 gqk(HIDDEN / 128, MROWS / 128, 2);
    qkv_gemm_kernel<<<gqk, 256>>>(x, Wq, Wk, Wv, 0);
    cudaEventRecord(ev_qk, 0);

    dim3 gs(SEQ / 128, SEQ / 128, HB);
    dim3 gav(SEQ / 128, HB);
    dim3 go(HIDDEN / 128, MROWS / 2 / 128);   // 16 row-tiles per batch

    // ---- half B (batch 1) on s_b ----
    cudaStreamWaitEvent(s_b, ev_qk, 0);
    scores_gemm_kernel<<<gs, 256, 0, s_b>>>(thr, HB);
    select_fast_kernel<<<HROWS / 256, 256, 0, s_b>>>(HROWS, 1);
    select_slow_kernel<<<32, 256, 0, s_b>>>(1);
    cudaStreamWaitEvent(s_b, ev_v, 0);
    av_gemm_kernel<<<gav, 256, 0, s_b>>>(thr, HB);
    out_gemm_kernel<<<go, 256, 0, s_b>>>(Wo, bo, out, MROWS / 2);
    cudaEventRecord(ev_b, s_b);

    // ---- half A (batch 0) on main ----
    scores_gemm_kernel<<<gs, 256>>>(thr, 0);
    select_fast_kernel<<<HROWS / 256, 256>>>(0, 0);
    select_slow_kernel<<<32, 256>>>(0);
    cudaStreamWaitEvent(0, ev_v, 0);
    av_gemm_kernel<<<gav, 256>>>(thr, 0);
    out_gemm_kernel<<<go, 256>>>(Wo, bo, out, 0);

    // join half B
    cudaStreamWaitEvent(0, ev_b, 0);
}